// round 2
// baseline (speedup 1.0000x reference)
#include <cuda_runtime.h>
#include <math.h>

#define N_NODES 50000
#define N_EDGES 800000
#define HID 128
#define IN_DIM 128
#define N_LAYERS 3
#define LN_EPS 1e-5f

// ---------------- scratch (static device globals; no runtime alloc) ----------
__device__ int   g_counts[N_NODES];
__device__ int   g_rowptr[N_NODES + 1];
__device__ int   g_cursor[N_NODES];
__device__ int   g_srcsorted[N_EDGES];
__device__ float g_agg[(size_t)N_NODES * HID];

// ---------------- CSR build ---------------------------------------------------
__global__ void k_zero_counts() {
    int i = blockIdx.x * blockDim.x + threadIdx.x;
    if (i < N_NODES) g_counts[i] = 0;
}

__global__ void k_hist(const int* __restrict__ dst) {
    int e = blockIdx.x * blockDim.x + threadIdx.x;
    if (e < N_EDGES) atomicAdd(&g_counts[dst[e]], 1);
}

// single-block sequential-chunk exclusive scan over 50000 counts
__global__ void k_scan() {
    __shared__ int buf[1024];
    __shared__ int carry_s;
    int tid = threadIdx.x;
    if (tid == 0) { carry_s = 0; g_rowptr[0] = 0; }
    __syncthreads();
    for (int base = 0; base < N_NODES; base += 1024) {
        int i = base + tid;
        int v = (i < N_NODES) ? g_counts[i] : 0;
        buf[tid] = v;
        __syncthreads();
        #pragma unroll
        for (int off = 1; off < 1024; off <<= 1) {
            int t = (tid >= off) ? buf[tid - off] : 0;
            __syncthreads();
            buf[tid] += t;
            __syncthreads();
        }
        int carry = carry_s;
        if (i < N_NODES) {
            int incl = carry + buf[tid];
            g_rowptr[i + 1] = incl;
            g_cursor[i]     = incl - v;   // segment start
        }
        __syncthreads();
        if (tid == 1023) carry_s = carry + buf[1023];
        __syncthreads();
    }
}

__global__ void k_scatter(const int* __restrict__ src, const int* __restrict__ dst) {
    int e = blockIdx.x * blockDim.x + threadIdx.x;
    if (e < N_EDGES) {
        int p = atomicAdd(&g_cursor[dst[e]], 1);
        g_srcsorted[p] = src[e];
    }
}

// ---------------- scatter-logsumexp: 1 block(128) per node, online LSE --------
__global__ void __launch_bounds__(128) k_lse(const float* __restrict__ h) {
    int n = blockIdx.x;
    int t = threadIdx.x;
    int beg = g_rowptr[n];
    int end = g_rowptr[n + 1];
    float out;
    if (beg == end) {
        out = 0.0f;                   // empty segment -> 0 (deg==0 mask)
    } else {
        float m = __int_as_float(0xff800000);   // -inf
        float s = 0.0f;
        for (int e = beg; e < end; ++e) {
            int src = g_srcsorted[e];                 // uniform across block
            float v = __ldg(&h[(size_t)src * HID + t]);
            float nm = fmaxf(m, v);
            // exp(-inf) == +0 per PTX ex2.approx; s==0 on first iter -> safe
            s = s * __expf(m - nm) + __expf(v - nm);
            m = nm;
        }
        out = m + __logf(s);          // tau == 1; s >= 1 so eps clamp moot
    }
    g_agg[(size_t)n * HID + t] = out;
}

// ---------------- fused GEMM kernels ------------------------------------------
// Block computes a 64x128 output tile. 256 threads, each owns 4 rows x 8 cols
// (cols tx*4+j and 64+tx*4+j). Row r is owned by the 16 lanes sharing ty, so
// LayerNorm reduces with shfl_xor over a 16-lane group.
#define BM 64
#define BN 128
#define BK 16

// MODE 0: h = x@Wi + bi  (K=128, no LN/relu/residual)
// MODE 1: y = [h|agg]@W + b ; h = 0.5*h + 0.5*relu(LN(y)*gamma+beta)  (K=256)
template <int MODE>
__global__ void __launch_bounds__(256) k_gemm(
    float* __restrict__ h,
    const float* __restrict__ A0,      // MODE0: x ; MODE1: h (first 128 K)
    const float* __restrict__ W,
    const float* __restrict__ bias,
    const float* __restrict__ gamma,
    const float* __restrict__ beta)
{
    __shared__ float As[BM][BK + 1];
    __shared__ float Bs[BK][BN];

    const int tid = threadIdx.x;
    const int tx  = tid & 15;          // 0..15 col group
    const int ty  = tid >> 4;          // 0..15 row group
    const int ty4 = ty * 4;
    const int rb  = blockIdx.x * BM;
    const int K   = (MODE == 0) ? 128 : 256;

    float acc[4][8];
    #pragma unroll
    for (int i = 0; i < 4; i++)
        #pragma unroll
        for (int j = 0; j < 8; j++) acc[i][j] = 0.0f;

    for (int k0 = 0; k0 < K; k0 += BK) {
        const float* Ap = (MODE == 1 && k0 >= 128) ? g_agg : A0;
        int ko = k0 & 127;

        // A tile: thread loads 4 elems, coalesced in 64B segments
        {
            int c  = tid & 15;
            int r0 = (tid >> 4) * 4;
            #pragma unroll
            for (int i = 0; i < 4; i++) {
                int row = rb + r0 + i;
                if (row >= N_NODES) row = N_NODES - 1;   // clamp; discarded later
                As[r0 + i][c] = Ap[(size_t)row * 128 + ko + c];
            }
        }
        // B tile: 512 float4, 2 per thread, fully coalesced
        {
            #pragma unroll
            for (int i = 0; i < 2; i++) {
                int f  = tid + i * 256;
                int k  = f >> 5;
                int n4 = f & 31;
                *(float4*)&Bs[k][n4 * 4] =
                    *(const float4*)&W[(size_t)(k0 + k) * 128 + n4 * 4];
            }
        }
        __syncthreads();

        #pragma unroll
        for (int k = 0; k < BK; k++) {
            float4 b0 = *(const float4*)&Bs[k][tx * 4];
            float4 b1 = *(const float4*)&Bs[k][64 + tx * 4];
            #pragma unroll
            for (int i = 0; i < 4; i++) {
                float a = As[ty4 + i][k];
                acc[i][0] = fmaf(a, b0.x, acc[i][0]);
                acc[i][1] = fmaf(a, b0.y, acc[i][1]);
                acc[i][2] = fmaf(a, b0.z, acc[i][2]);
                acc[i][3] = fmaf(a, b0.w, acc[i][3]);
                acc[i][4] = fmaf(a, b1.x, acc[i][4]);
                acc[i][5] = fmaf(a, b1.y, acc[i][5]);
                acc[i][6] = fmaf(a, b1.z, acc[i][6]);
                acc[i][7] = fmaf(a, b1.w, acc[i][7]);
            }
        }
        __syncthreads();
    }

    // per-col params (cols: j<4 -> tx*4+j ; j>=4 -> 64+tx*4+j-4)
    float bv[8], gv[8], ev[8];
    #pragma unroll
    for (int j = 0; j < 8; j++) {
        int c = (j < 4) ? (tx * 4 + j) : (64 + tx * 4 + j - 4);
        bv[j] = bias[c];
        if (MODE == 1) { gv[j] = gamma[c]; ev[j] = beta[c]; }
    }

    #pragma unroll
    for (int i = 0; i < 4; i++) {
        int row = rb + ty4 + i;
        if (MODE == 0) {
            if (row < N_NODES) {
                #pragma unroll
                for (int j = 0; j < 8; j++) {
                    int c = (j < 4) ? (tx * 4 + j) : (64 + tx * 4 + j - 4);
                    h[(size_t)row * 128 + c] = acc[i][j] + bv[j];
                }
            }
        } else {
            // y = gemm + bias ; LN over the 128 cols of this row
            float s1 = 0.0f, s2 = 0.0f;
            #pragma unroll
            for (int j = 0; j < 8; j++) {
                float y = acc[i][j] + bv[j];
                acc[i][j] = y;
                s1 += y;
                s2 += y * y;
            }
            #pragma unroll
            for (int o = 8; o >= 1; o >>= 1) {
                s1 += __shfl_xor_sync(0xffffffffu, s1, o);
                s2 += __shfl_xor_sync(0xffffffffu, s2, o);
            }
            float mu   = s1 * (1.0f / 128.0f);
            float var  = s2 * (1.0f / 128.0f) - mu * mu;
            float rstd = rsqrtf(var + LN_EPS);
            if (row < N_NODES) {
                #pragma unroll
                for (int j = 0; j < 8; j++) {
                    int c = (j < 4) ? (tx * 4 + j) : (64 + tx * 4 + j - 4);
                    float hn = (acc[i][j] - mu) * rstd * gv[j] + ev[j];
                    hn = fmaxf(hn, 0.0f);
                    float ho = h[(size_t)row * 128 + c];
                    h[(size_t)row * 128 + c] = 0.5f * (ho + hn);
                }
            }
        }
    }
}

// ---------------- launch ------------------------------------------------------
extern "C" void kernel_launch(void* const* d_in, const int* in_sizes, int n_in,
                              void* d_out, int out_size)
{
    const float* x        = (const float*)d_in[0];
    const int*   edge_src = (const int*)  d_in[1];
    const int*   edge_dst = (const int*)  d_in[2];
    const float* Wi       = (const float*)d_in[3];
    const float* bi       = (const float*)d_in[4];
    const float* Wl       = (const float*)d_in[5];
    const float* bl       = (const float*)d_in[6];
    const float* gamma    = (const float*)d_in[7];
    const float* beta     = (const float*)d_in[8];
    float* h = (float*)d_out;

    // CSR by dst (rebuilt every call: deterministic work)
    k_zero_counts<<<(N_NODES + 255) / 256, 256>>>();
    k_hist<<<(N_EDGES + 255) / 256, 256>>>(edge_dst);
    k_scan<<<1, 1024>>>();
    k_scatter<<<(N_EDGES + 255) / 256, 256>>>(edge_src, edge_dst);

    const int gblocks = (N_NODES + BM - 1) / BM;

    // input projection
    k_gemm<0><<<gblocks, 256>>>(h, x, Wi, bi, nullptr, nullptr);

    for (int l = 0; l < N_LAYERS; l++) {
        k_lse<<<N_NODES, 128>>>(h);
        k_gemm<1><<<gblocks, 256>>>(h, h,
                                    Wl + (size_t)l * 256 * 128,
                                    bl + l * 128,
                                    gamma + l * 128,
                                    beta + l * 128);
    }
}

// round 4
// speedup vs baseline: 1.5172x; 1.5172x over previous
#include <cuda_runtime.h>
#include <cuda_bf16.h>
#include <math.h>
#include <stdint.h>

#define N_NODES 50000
#define N_EDGES 800000
#define HID 128
#define N_LAYERS 3
#define LN_EPS 1e-5f

// ---------------- scratch (static device globals; no runtime alloc) ----------
__device__ int   g_counts[N_NODES];
__device__ int   g_rowptr[N_NODES + 1];
__device__ int   g_cursor[N_NODES];
__device__ int   g_bsum[256];
__device__ int   g_bsumx[256];
__device__ int   g_srcsorted[N_EDGES];
__device__ float g_agg[(size_t)N_NODES * HID];
// preconverted weights, B-layout [slot][n=128][k=256] bf16 hi/lo (slot0=Wi, k<128 used)
__device__ __nv_bfloat16 g_Bh[4 * 128 * 256];
__device__ __nv_bfloat16 g_Bl[4 * 128 * 256];

// ================= warp MMA helpers (sm_100 HMMA path) ========================
__device__ __forceinline__ uint32_t smem_u32(const void* p) {
    uint32_t a;
    asm("{ .reg .u64 t; cvta.to.shared.u64 t, %1; cvt.u32.u64 %0, t; }" : "=r"(a) : "l"(p));
    return a;
}
__device__ __forceinline__ void ldm4(uint32_t* r, uint32_t addr) {
    asm volatile("ldmatrix.sync.aligned.m8n8.x4.shared.b16 {%0,%1,%2,%3}, [%4];"
                 : "=r"(r[0]), "=r"(r[1]), "=r"(r[2]), "=r"(r[3]) : "r"(addr));
}
__device__ __forceinline__ void mma16816(float* d, const uint32_t* a, uint32_t b0, uint32_t b1) {
    asm volatile(
        "mma.sync.aligned.m16n8k16.row.col.f32.bf16.bf16.f32 "
        "{%0,%1,%2,%3}, {%4,%5,%6,%7}, {%8,%9}, {%0,%1,%2,%3};"
        : "+f"(d[0]), "+f"(d[1]), "+f"(d[2]), "+f"(d[3])
        : "r"(a[0]), "r"(a[1]), "r"(a[2]), "r"(a[3]), "r"(b0), "r"(b1));
}

// ---------------- CSR build ---------------------------------------------------
__global__ void k_zero_counts() {
    int i = blockIdx.x * blockDim.x + threadIdx.x;
    if (i < N_NODES) g_counts[i] = 0;
}
__global__ void k_hist(const int* __restrict__ dst) {
    int e = blockIdx.x * blockDim.x + threadIdx.x;
    if (e < N_EDGES) atomicAdd(&g_counts[dst[e]], 1);
}
__global__ void k_scan1() {
    __shared__ int wsum[8];
    int b = blockIdx.x, t = threadIdx.x;
    int i = b * 256 + t;
    int v = (i < N_NODES) ? g_counts[i] : 0;
    int lane = t & 31, w = t >> 5;
    int x = v;
    #pragma unroll
    for (int off = 1; off < 32; off <<= 1) {
        int n = __shfl_up_sync(0xffffffffu, x, off);
        if (lane >= off) x += n;
    }
    if (lane == 31) wsum[w] = x;
    __syncthreads();
    if (t < 8) {
        int a = wsum[t];
        #pragma unroll
        for (int off = 1; off < 8; off <<= 1) {
            int n = __shfl_up_sync(0xffu, a, off);
            if (t >= off) a += n;
        }
        wsum[t] = a;
    }
    __syncthreads();
    int incl = x + (w > 0 ? wsum[w - 1] : 0);
    if (i < N_NODES) g_rowptr[i + 1] = incl;
    if (t == 255) g_bsum[b] = incl;
}
__global__ void k_scan2() {
    __shared__ int buf[256];
    int t = threadIdx.x;
    int nb = (N_NODES + 255) / 256;
    int v = (t < nb) ? g_bsum[t] : 0;
    buf[t] = v;
    __syncthreads();
    #pragma unroll
    for (int off = 1; off < 256; off <<= 1) {
        int x = (t >= off) ? buf[t - off] : 0;
        __syncthreads();
        buf[t] += x;
        __syncthreads();
    }
    g_bsumx[t] = buf[t] - v;   // exclusive
}
__global__ void k_scan3() {
    int b = blockIdx.x, t = threadIdx.x;
    int i = b * 256 + t;
    if (i < N_NODES) {
        int r = g_rowptr[i + 1] + g_bsumx[b];
        g_rowptr[i + 1] = r;
        g_cursor[i] = r - g_counts[i];
    }
    if (i == 0) g_rowptr[0] = 0;
}
__global__ void k_scatter(const int* __restrict__ src, const int* __restrict__ dst) {
    int e = blockIdx.x * blockDim.x + threadIdx.x;
    if (e < N_EDGES) {
        int p = atomicAdd(&g_cursor[dst[e]], 1);
        g_srcsorted[p] = src[e];
    }
}

// ---------------- weight preconversion: B[slot][n][k] = W[k][n] hi/lo ---------
__global__ void k_prep_b(const float* __restrict__ Wi, const float* __restrict__ Wl) {
    int idx = blockIdx.x * blockDim.x + threadIdx.x;   // 4*128*256
    int slot = idx >> 15;
    int rem  = idx & 32767;
    int n = rem >> 8;
    int k = rem & 255;
    float v;
    if (slot == 0) v = (k < 128) ? Wi[k * 128 + n] : 0.0f;
    else           v = Wl[(size_t)(slot - 1) * 256 * 128 + k * 128 + n];
    __nv_bfloat16 hi = __float2bfloat16(v);
    __nv_bfloat16 lo = __float2bfloat16(v - __bfloat162float(hi));
    g_Bh[idx] = hi;
    g_Bl[idx] = lo;
}

// ---------------- scatter-logsumexp: direct exp (h bounded), 1 exp/elem -------
__global__ void __launch_bounds__(128) k_lse(const float* __restrict__ h) {
    int n = blockIdx.x;
    int t = threadIdx.x;
    int beg = g_rowptr[n];
    int end = g_rowptr[n + 1];
    float out;
    if (beg == end) {
        out = 0.0f;
    } else {
        float a0 = 0.f, a1 = 0.f, a2 = 0.f, a3 = 0.f;
        int e = beg;
        for (; e + 4 <= end; e += 4) {
            int s0 = g_srcsorted[e];
            int s1 = g_srcsorted[e + 1];
            int s2 = g_srcsorted[e + 2];
            int s3 = g_srcsorted[e + 3];
            a0 += __expf(__ldg(&h[(size_t)s0 * HID + t]));
            a1 += __expf(__ldg(&h[(size_t)s1 * HID + t]));
            a2 += __expf(__ldg(&h[(size_t)s2 * HID + t]));
            a3 += __expf(__ldg(&h[(size_t)s3 * HID + t]));
        }
        for (; e < end; ++e)
            a0 += __expf(__ldg(&h[(size_t)g_srcsorted[e] * HID + t]));
        out = __logf((a0 + a1) + (a2 + a3));
    }
    g_agg[(size_t)n * HID + t] = out;
}

// ---------------- tensor-core fused GEMM (mma.sync bf16 hi/lo split) ----------
// CTA: 256 threads (8 warps, 4x2), 128x128 output tile, K in 64-wide chunks.
// SMEM rows padded to 72 bf16 (144B) -> ldmatrix conflict-free.
#define ASTRIDE 72           // bf16 elems per smem row (144 B)
#define S_AH 0u
#define S_AL 18432u
#define S_BH 36864u
#define S_BL 55296u
#define OPER_BYTES 73728
#define DSTRIDE 132          // fp32 elems per Ds row
#define SMEM_BYTES 73728     // >= 128*132*4 = 67584

template <int KT>
__global__ void __launch_bounds__(256, 1) k_mma_gemm(
    float* __restrict__ h,
    const float* __restrict__ A0,
    const __nv_bfloat16* __restrict__ Bh,
    const __nv_bfloat16* __restrict__ Bl,
    const float* __restrict__ bias,
    const float* __restrict__ gamma,
    const float* __restrict__ beta)
{
    extern __shared__ char smem[];
    const uint32_t sb = smem_u32(smem);
    const int tid  = threadIdx.x;
    const int lane = tid & 31;
    const int w    = tid >> 5;
    const int wm   = w >> 1;        // 0..3
    const int wn   = w & 1;         // 0..1
    const int rb   = blockIdx.x * 128;

    float acc[2][8][4];
    #pragma unroll
    for (int mt = 0; mt < 2; mt++)
        #pragma unroll
        for (int g = 0; g < 8; g++)
            #pragma unroll
            for (int q = 0; q < 4; q++) acc[mt][g][q] = 0.0f;

    // ldmatrix source addresses (chunk-invariant parts)
    // A: row = wm*32 + mt*16 + (lane&15), col bytes = (lane>>4)*16 + ks*32
    const uint32_t a_row_off = (uint32_t)((wm * 32 + (lane & 15)) * ASTRIDE * 2 + (lane >> 4) * 16);
    // B: row = wn*64 + i*16 + (lane&7) + ((lane&16)>>1), col bytes = ((lane>>3)&1)*16 + ks*32
    const uint32_t b_row_off = (uint32_t)((wn * 64 + (lane & 7) + ((lane & 16) >> 1)) * ASTRIDE * 2
                                          + ((lane >> 3) & 1) * 16);

    constexpr int NCH = KT / 64;
    for (int c = 0; c < NCH; c++) {
        const float* Ap = (KT == 256 && c >= 2) ? g_agg : A0;
        const int kbase = (c * 64) & 127;

        __syncthreads();
        // --- A chunk: 128 rows x 64 fp32 -> bf16 hi/lo ------------------------
        #pragma unroll
        for (int it = 0; it < 8; it++) {
            int idx = tid + it * 256;           // 128*16 float4 slots
            int row = idx >> 4, q = idx & 15;
            int grow = rb + row;
            if (grow >= N_NODES) grow = N_NODES - 1;
            float4 v = *(const float4*)&Ap[(size_t)grow * 128 + kbase + q * 4];
            __nv_bfloat16 h0 = __float2bfloat16(v.x);
            __nv_bfloat16 h1 = __float2bfloat16(v.y);
            __nv_bfloat16 h2 = __float2bfloat16(v.z);
            __nv_bfloat16 h3 = __float2bfloat16(v.w);
            __nv_bfloat16 l0 = __float2bfloat16(v.x - __bfloat162float(h0));
            __nv_bfloat16 l1 = __float2bfloat16(v.y - __bfloat162float(h1));
            __nv_bfloat16 l2 = __float2bfloat16(v.z - __bfloat162float(h2));
            __nv_bfloat16 l3 = __float2bfloat16(v.w - __bfloat162float(h3));
            uint32_t wh0 = ((uint32_t)*(uint16_t*)&h1 << 16) | *(uint16_t*)&h0;
            uint32_t wh1 = ((uint32_t)*(uint16_t*)&h3 << 16) | *(uint16_t*)&h2;
            uint32_t wl0 = ((uint32_t)*(uint16_t*)&l1 << 16) | *(uint16_t*)&l0;
            uint32_t wl1 = ((uint32_t)*(uint16_t*)&l3 << 16) | *(uint16_t*)&l2;
            uint32_t so = (uint32_t)(row * ASTRIDE + q * 4) * 2;   // bytes
            *(uint32_t*)(smem + S_AH + so)     = wh0;
            *(uint32_t*)(smem + S_AH + so + 4) = wh1;
            *(uint32_t*)(smem + S_AL + so)     = wl0;
            *(uint32_t*)(smem + S_AL + so + 4) = wl1;
        }
        // --- B chunk: 128 n-rows x 64 bf16 (preconverted) ---------------------
        #pragma unroll
        for (int it = 0; it < 4; it++) {
            int idx = tid + it * 256;           // 128*8 uint4 slots
            int row = idx >> 3, q = idx & 7;
            size_t ge = (size_t)row * 256 + c * 64 + q * 8;   // bf16 elems
            uint32_t so = (uint32_t)(row * ASTRIDE + q * 8) * 2;
            *(uint4*)(smem + S_BH + so) = *(const uint4*)&Bh[ge];
            *(uint4*)(smem + S_BL + so) = *(const uint4*)&Bl[ge];
        }
        __syncthreads();

        // --- 4 k-steps of 16 --------------------------------------------------
        #pragma unroll
        for (int ks = 0; ks < 4; ks++) {
            const uint32_t kb = ks * 32;   // byte offset of k0 within row
            uint32_t ah[2][4], al[2][4];
            #pragma unroll
            for (int mt = 0; mt < 2; mt++) {
                uint32_t ra = a_row_off + (uint32_t)(mt * 16 * ASTRIDE * 2) + kb;
                ldm4(ah[mt], sb + S_AH + ra);
                ldm4(al[mt], sb + S_AL + ra);
            }
            uint32_t bh[4][4], bl[4][4];
            #pragma unroll
            for (int i = 0; i < 4; i++) {
                uint32_t rbo = b_row_off + (uint32_t)(i * 16 * ASTRIDE * 2) + kb;
                ldm4(bh[i], sb + S_BH + rbo);
                ldm4(bl[i], sb + S_BL + rbo);
            }
            #pragma unroll
            for (int mt = 0; mt < 2; mt++) {
                #pragma unroll
                for (int i = 0; i < 4; i++) {
                    mma16816(acc[mt][2 * i],     ah[mt], bh[i][0], bh[i][1]);
                    mma16816(acc[mt][2 * i + 1], ah[mt], bh[i][2], bh[i][3]);
                    mma16816(acc[mt][2 * i],     ah[mt], bl[i][0], bl[i][1]);
                    mma16816(acc[mt][2 * i + 1], ah[mt], bl[i][2], bl[i][3]);
                    mma16816(acc[mt][2 * i],     al[mt], bh[i][0], bh[i][1]);
                    mma16816(acc[mt][2 * i + 1], al[mt], bh[i][2], bh[i][3]);
                }
            }
        }
    }

    // ---------------- stage D to smem (fp32, stride 132) ----------------------
    __syncthreads();
    float* Ds = (float*)smem;
    {
        const int r0 = wm * 32 + (lane >> 2);
        const int c0 = wn * 64 + (lane & 3) * 2;
        #pragma unroll
        for (int mt = 0; mt < 2; mt++) {
            #pragma unroll
            for (int g = 0; g < 8; g++) {
                int r = r0 + mt * 16;
                int cc = c0 + g * 8;
                *(float2*)&Ds[(r)     * DSTRIDE + cc] = make_float2(acc[mt][g][0], acc[mt][g][1]);
                *(float2*)&Ds[(r + 8) * DSTRIDE + cc] = make_float2(acc[mt][g][2], acc[mt][g][3]);
            }
        }
    }
    __syncthreads();

    // ---------------- epilogue: thread t -> (row t/2, half t&1) ---------------
    const int row  = tid >> 1;
    const int half = tid & 1;
    const int grow = rb + row;
    const bool ok  = grow < N_NODES;
    const float* drow = &Ds[row * DSTRIDE + half * 64];

    if (KT == 128) {
        if (ok) {
            #pragma unroll
            for (int j4 = 0; j4 < 16; j4++) {
                float4 o;
                o.x = drow[j4 * 4 + 0] + __ldg(&bias[half * 64 + j4 * 4 + 0]);
                o.y = drow[j4 * 4 + 1] + __ldg(&bias[half * 64 + j4 * 4 + 1]);
                o.z = drow[j4 * 4 + 2] + __ldg(&bias[half * 64 + j4 * 4 + 2]);
                o.w = drow[j4 * 4 + 3] + __ldg(&bias[half * 64 + j4 * 4 + 3]);
                *(float4*)&h[(size_t)grow * 128 + half * 64 + j4 * 4] = o;
            }
        }
    } else {
        float s1 = 0.f, s2 = 0.f;
        #pragma unroll
        for (int j = 0; j < 64; j++) {
            float y = drow[j] + __ldg(&bias[half * 64 + j]);
            s1 += y;
            s2 += y * y;
        }
        s1 += __shfl_xor_sync(0xffffffffu, s1, 1);
        s2 += __shfl_xor_sync(0xffffffffu, s2, 1);
        float mu   = s1 * (1.0f / 128.0f);
        float var  = s2 * (1.0f / 128.0f) - mu * mu;
        float rstd = rsqrtf(var + LN_EPS);
        if (ok) {
            #pragma unroll
            for (int j4 = 0; j4 < 16; j4++) {
                float4 old = *(const float4*)&h[(size_t)grow * 128 + half * 64 + j4 * 4];
                float4 o;
                #pragma unroll
                for (int q = 0; q < 4; q++) {
                    int col = half * 64 + j4 * 4 + q;
                    float y  = drow[j4 * 4 + q] + __ldg(&bias[col]);
                    float hn = (y - mu) * rstd * __ldg(&gamma[col]) + __ldg(&beta[col]);
                    hn = fmaxf(hn, 0.0f);
                    (&o.x)[q] = 0.5f * ((&old.x)[q] + hn);
                }
                *(float4*)&h[(size_t)grow * 128 + half * 64 + j4 * 4] = o;
            }
        }
    }
}

// ---------------- launch ------------------------------------------------------
extern "C" void kernel_launch(void* const* d_in, const int* in_sizes, int n_in,
                              void* d_out, int out_size)
{
    const float* x        = (const float*)d_in[0];
    const int*   edge_src = (const int*)  d_in[1];
    const int*   edge_dst = (const int*)  d_in[2];
    const float* Wi       = (const float*)d_in[3];
    const float* bi       = (const float*)d_in[4];
    const float* Wl       = (const float*)d_in[5];
    const float* bl       = (const float*)d_in[6];
    const float* gamma    = (const float*)d_in[7];
    const float* beta     = (const float*)d_in[8];
    float* h = (float*)d_out;

    cudaFuncSetAttribute(k_mma_gemm<128>, cudaFuncAttributeMaxDynamicSharedMemorySize, SMEM_BYTES);
    cudaFuncSetAttribute(k_mma_gemm<256>, cudaFuncAttributeMaxDynamicSharedMemorySize, SMEM_BYTES);

    const int nb = (N_NODES + 255) / 256;       // 196

    k_prep_b<<<(4 * 128 * 256) / 256, 256>>>(Wi, Wl);
    k_zero_counts<<<nb, 256>>>();
    k_hist<<<(N_EDGES + 255) / 256, 256>>>(edge_dst);
    k_scan1<<<nb, 256>>>();
    k_scan2<<<1, 256>>>();
    k_scan3<<<nb, 256>>>();
    k_scatter<<<(N_EDGES + 255) / 256, 256>>>(edge_src, edge_dst);

    const int gb = (N_NODES + 127) / 128;       // 391

    __nv_bfloat16* bh0;  __nv_bfloat16* bl0;
    cudaGetSymbolAddress((void**)&bh0, g_Bh);
    cudaGetSymbolAddress((void**)&bl0, g_Bl);

    k_mma_gemm<128><<<gb, 256, SMEM_BYTES>>>(h, x, bh0, bl0, bi, nullptr, nullptr);

    for (int l = 0; l < N_LAYERS; l++) {
        k_lse<<<N_NODES, 128>>>(h);
        k_mma_gemm<256><<<gb, 256, SMEM_BYTES>>>(
            h, h,
            bh0 + (size_t)(l + 1) * 128 * 256,
            bl0 + (size_t)(l + 1) * 128 * 256,
            bl + l * 128, gamma + l * 128, beta + l * 128);
    }
}

// round 5
// speedup vs baseline: 1.5586x; 1.0273x over previous
#include <cuda_runtime.h>
#include <cuda_bf16.h>
#include <cuda_fp16.h>
#include <math.h>
#include <stdint.h>

#define N_NODES 50000
#define N_EDGES 800000
#define HID 128
#define N_LAYERS 3
#define LN_EPS 1e-5f

// ---------------- scratch (static device globals; no runtime alloc) ----------
__device__ int   g_counts[N_NODES];
__device__ int   g_rowptr[N_NODES + 1];
__device__ int   g_cursor[N_NODES];
__device__ int   g_bsum[256];
__device__ int   g_bsumx[256];
__device__ int   g_srcsorted[N_EDGES];
// h (A, first 128 k) as bf16 hi/lo ; agg (A, second 128 k) as bf16 hi/lo
__device__ __nv_bfloat16 g_Ahh[(size_t)N_NODES * HID];
__device__ __nv_bfloat16 g_Ahl[(size_t)N_NODES * HID];
__device__ __nv_bfloat16 g_Agh[(size_t)N_NODES * HID];
__device__ __nv_bfloat16 g_Agl[(size_t)N_NODES * HID];
// exp(h) table, fp16
__device__ __half g_e[(size_t)N_NODES * HID];
// preconverted weights, B-layout [slot][n=128][k=256] bf16 hi/lo (slot0=Wi, k<128 used)
__device__ __nv_bfloat16 g_Bh[4 * 128 * 256];
__device__ __nv_bfloat16 g_Bl[4 * 128 * 256];

// ================= helpers ====================================================
__device__ __forceinline__ uint32_t smem_u32(const void* p) {
    uint32_t a;
    asm("{ .reg .u64 t; cvta.to.shared.u64 t, %1; cvt.u32.u64 %0, t; }" : "=r"(a) : "l"(p));
    return a;
}
__device__ __forceinline__ void ldm4(uint32_t* r, uint32_t addr) {
    asm volatile("ldmatrix.sync.aligned.m8n8.x4.shared.b16 {%0,%1,%2,%3}, [%4];"
                 : "=r"(r[0]), "=r"(r[1]), "=r"(r[2]), "=r"(r[3]) : "r"(addr));
}
__device__ __forceinline__ void mma16816(float* d, const uint32_t* a, uint32_t b0, uint32_t b1) {
    asm volatile(
        "mma.sync.aligned.m16n8k16.row.col.f32.bf16.bf16.f32 "
        "{%0,%1,%2,%3}, {%4,%5,%6,%7}, {%8,%9}, {%0,%1,%2,%3};"
        : "+f"(d[0]), "+f"(d[1]), "+f"(d[2]), "+f"(d[3])
        : "r"(a[0]), "r"(a[1]), "r"(a[2]), "r"(a[3]), "r"(b0), "r"(b1));
}
__device__ __forceinline__ uint32_t pack_bf2(__nv_bfloat16 a, __nv_bfloat16 b) {
    return ((uint32_t)*(uint16_t*)&b << 16) | *(uint16_t*)&a;
}
__device__ __forceinline__ uint32_t pack_h2(__half a, __half b) {
    return ((uint32_t)*(uint16_t*)&b << 16) | *(uint16_t*)&a;
}

// ---------------- CSR build ---------------------------------------------------
__global__ void k_zero_counts() {
    int i = blockIdx.x * blockDim.x + threadIdx.x;
    if (i < N_NODES) g_counts[i] = 0;
}
__global__ void k_hist(const int* __restrict__ dst) {
    int e = blockIdx.x * blockDim.x + threadIdx.x;
    if (e < N_EDGES) atomicAdd(&g_counts[dst[e]], 1);
}
__global__ void k_scan1() {
    __shared__ int wsum[8];
    int b = blockIdx.x, t = threadIdx.x;
    int i = b * 256 + t;
    int v = (i < N_NODES) ? g_counts[i] : 0;
    int lane = t & 31, w = t >> 5;
    int x = v;
    #pragma unroll
    for (int off = 1; off < 32; off <<= 1) {
        int n = __shfl_up_sync(0xffffffffu, x, off);
        if (lane >= off) x += n;
    }
    if (lane == 31) wsum[w] = x;
    __syncthreads();
    if (t < 8) {
        int a = wsum[t];
        #pragma unroll
        for (int off = 1; off < 8; off <<= 1) {
            int n = __shfl_up_sync(0xffu, a, off);
            if (t >= off) a += n;
        }
        wsum[t] = a;
    }
    __syncthreads();
    int incl = x + (w > 0 ? wsum[w - 1] : 0);
    if (i < N_NODES) g_rowptr[i + 1] = incl;
    if (t == 255) g_bsum[b] = incl;
}
__global__ void k_scan2() {
    __shared__ int buf[256];
    int t = threadIdx.x;
    int nb = (N_NODES + 255) / 256;
    int v = (t < nb) ? g_bsum[t] : 0;
    buf[t] = v;
    __syncthreads();
    #pragma unroll
    for (int off = 1; off < 256; off <<= 1) {
        int x = (t >= off) ? buf[t - off] : 0;
        __syncthreads();
        buf[t] += x;
        __syncthreads();
    }
    g_bsumx[t] = buf[t] - v;   // exclusive
}
__global__ void k_scan3() {
    int b = blockIdx.x, t = threadIdx.x;
    int i = b * 256 + t;
    if (i < N_NODES) {
        int r = g_rowptr[i + 1] + g_bsumx[b];
        g_rowptr[i + 1] = r;
        g_cursor[i] = r - g_counts[i];
    }
    if (i == 0) g_rowptr[0] = 0;
}
__global__ void k_scatter(const int* __restrict__ src, const int* __restrict__ dst) {
    int e = blockIdx.x * blockDim.x + threadIdx.x;
    if (e < N_EDGES) {
        int p = atomicAdd(&g_cursor[dst[e]], 1);
        g_srcsorted[p] = src[e];
    }
}

// ---------------- weight preconversion: B[slot][n][k] = W[k][n] hi/lo ---------
__global__ void k_prep_b(const float* __restrict__ Wi, const float* __restrict__ Wl) {
    int idx = blockIdx.x * blockDim.x + threadIdx.x;   // 4*128*256
    int slot = idx >> 15;
    int rem  = idx & 32767;
    int n = rem >> 8;
    int k = rem & 255;
    float v;
    if (slot == 0) v = (k < 128) ? Wi[k * 128 + n] : 0.0f;
    else           v = Wl[(size_t)(slot - 1) * 256 * 128 + k * 128 + n];
    __nv_bfloat16 hi = __float2bfloat16(v);
    __nv_bfloat16 lo = __float2bfloat16(v - __bfloat162float(hi));
    g_Bh[idx] = hi;
    g_Bl[idx] = lo;
}

// ---------------- x -> bf16 hi/lo (input projection A operand) ----------------
__global__ void k_prep_ax(const float* __restrict__ x) {
    int idx = blockIdx.x * blockDim.x + threadIdx.x;   // N_NODES*32 float4 slots
    if (idx >= N_NODES * 32) return;
    float4 v = ((const float4*)x)[idx];
    __nv_bfloat16 h0 = __float2bfloat16(v.x);
    __nv_bfloat16 h1 = __float2bfloat16(v.y);
    __nv_bfloat16 h2 = __float2bfloat16(v.z);
    __nv_bfloat16 h3 = __float2bfloat16(v.w);
    uint2 ph = make_uint2(pack_bf2(h0, h1), pack_bf2(h2, h3));
    uint2 pl = make_uint2(
        pack_bf2(__float2bfloat16(v.x - __bfloat162float(h0)),
                 __float2bfloat16(v.y - __bfloat162float(h1))),
        pack_bf2(__float2bfloat16(v.z - __bfloat162float(h2)),
                 __float2bfloat16(v.w - __bfloat162float(h3))));
    ((uint2*)g_Ahh)[idx] = ph;
    ((uint2*)g_Ahl)[idx] = pl;
}

// ---------------- scatter-logsumexp: gather precomputed exp (fp16) ------------
// Block = 128 threads = 2 nodes x 64 threads; thread handles column pair (2t,2t+1).
__global__ void __launch_bounds__(128) k_lse() {
    int sub = threadIdx.x >> 6;
    int t   = threadIdx.x & 63;
    int n   = blockIdx.x * 2 + sub;
    if (n >= N_NODES) return;
    int beg = g_rowptr[n];
    int end = g_rowptr[n + 1];
    float vx, vy;
    if (beg == end) {
        vx = 0.0f; vy = 0.0f;
    } else {
        const __half2* E = (const __half2*)g_e;
        float2 a0 = make_float2(0.f, 0.f), a1 = make_float2(0.f, 0.f);
        float2 a2 = make_float2(0.f, 0.f), a3 = make_float2(0.f, 0.f);
        int e = beg;
        for (; e + 4 <= end; e += 4) {
            int s0 = __ldg(&g_srcsorted[e]);
            int s1 = __ldg(&g_srcsorted[e + 1]);
            int s2 = __ldg(&g_srcsorted[e + 2]);
            int s3 = __ldg(&g_srcsorted[e + 3]);
            float2 f0 = __half22float2(__ldg(&E[s0 * 64 + t]));
            float2 f1 = __half22float2(__ldg(&E[s1 * 64 + t]));
            float2 f2 = __half22float2(__ldg(&E[s2 * 64 + t]));
            float2 f3 = __half22float2(__ldg(&E[s3 * 64 + t]));
            a0.x += f0.x; a0.y += f0.y;
            a1.x += f1.x; a1.y += f1.y;
            a2.x += f2.x; a2.y += f2.y;
            a3.x += f3.x; a3.y += f3.y;
        }
        for (; e < end; ++e) {
            int s = __ldg(&g_srcsorted[e]);
            float2 f = __half22float2(__ldg(&E[s * 64 + t]));
            a0.x += f.x; a0.y += f.y;
        }
        vx = __logf((a0.x + a1.x) + (a2.x + a3.x));
        vy = __logf((a0.y + a1.y) + (a2.y + a3.y));
    }
    // write agg as bf16 hi/lo pairs
    __nv_bfloat16 hx = __float2bfloat16(vx);
    __nv_bfloat16 hy = __float2bfloat16(vy);
    size_t off = ((size_t)n * 128 + 2 * t) >> 1;   // uint32 index
    ((uint32_t*)g_Agh)[off] = pack_bf2(hx, hy);
    ((uint32_t*)g_Agl)[off] = pack_bf2(__float2bfloat16(vx - __bfloat162float(hx)),
                                       __float2bfloat16(vy - __bfloat162float(hy)));
}

// ---------------- tensor-core fused GEMM (mma.sync bf16 hi/lo split) ----------
// CTA: 256 threads (8 warps, 4x2), 128x128 output tile, K in 64-wide chunks.
// SMEM rows padded to 72 bf16 (144B) -> ldmatrix conflict-free.
#define ASTRIDE 72           // bf16 elems per smem row (144 B)
#define S_AH 0u
#define S_AL 18432u
#define S_BH 36864u
#define S_BL 55296u
#define DSTRIDE 132          // fp32 elems per Ds row
#define SMEM_BYTES 73728     // >= 128*132*4 = 67584

template <int KT, bool WAUX>
__global__ void __launch_bounds__(256, 1) k_mma_gemm(
    float* __restrict__ h,
    const __nv_bfloat16* __restrict__ Bh,
    const __nv_bfloat16* __restrict__ Bl,
    const float* __restrict__ bias,
    const float* __restrict__ gamma,
    const float* __restrict__ beta)
{
    extern __shared__ char smem[];
    const uint32_t sb = smem_u32(smem);
    const int tid  = threadIdx.x;
    const int lane = tid & 31;
    const int w    = tid >> 5;
    const int wm   = w >> 1;        // 0..3
    const int wn   = w & 1;         // 0..1
    const int rb   = blockIdx.x * 128;

    float acc[2][8][4];
    #pragma unroll
    for (int mt = 0; mt < 2; mt++)
        #pragma unroll
        for (int g = 0; g < 8; g++)
            #pragma unroll
            for (int q = 0; q < 4; q++) acc[mt][g][q] = 0.0f;

    // ldmatrix source addresses (chunk-invariant parts)
    const uint32_t a_row_off = (uint32_t)((wm * 32 + (lane & 15)) * ASTRIDE * 2 + (lane >> 4) * 16);
    const uint32_t b_row_off = (uint32_t)((wn * 64 + (lane & 7) + ((lane & 16) >> 1)) * ASTRIDE * 2
                                          + ((lane >> 3) & 1) * 16);

    constexpr int NCH = KT / 64;
    for (int c = 0; c < NCH; c++) {
        const __nv_bfloat16* Ah = (KT == 256 && c >= 2) ? g_Agh : g_Ahh;
        const __nv_bfloat16* Al = (KT == 256 && c >= 2) ? g_Agl : g_Ahl;
        const int kbase = (c * 64) & 127;

        __syncthreads();
        // --- A chunk: pure uint4 copies (preconverted bf16 hi/lo) -------------
        #pragma unroll
        for (int it = 0; it < 4; it++) {
            int idx = tid + it * 256;           // 128*8 uint4 slots
            int row = idx >> 3, q = idx & 7;
            int grow = rb + row;
            if (grow >= N_NODES) grow = N_NODES - 1;
            size_t ge = (size_t)grow * 128 + kbase + q * 8;
            uint32_t so = (uint32_t)(row * ASTRIDE + q * 8) * 2;
            *(uint4*)(smem + S_AH + so) = *(const uint4*)&Ah[ge];
            *(uint4*)(smem + S_AL + so) = *(const uint4*)&Al[ge];
        }
        // --- B chunk ----------------------------------------------------------
        #pragma unroll
        for (int it = 0; it < 4; it++) {
            int idx = tid + it * 256;           // 128*8 uint4 slots
            int row = idx >> 3, q = idx & 7;
            size_t ge = (size_t)row * 256 + c * 64 + q * 8;
            uint32_t so = (uint32_t)(row * ASTRIDE + q * 8) * 2;
            *(uint4*)(smem + S_BH + so) = *(const uint4*)&Bh[ge];
            *(uint4*)(smem + S_BL + so) = *(const uint4*)&Bl[ge];
        }
        __syncthreads();

        // --- 4 k-steps of 16 --------------------------------------------------
        #pragma unroll
        for (int ks = 0; ks < 4; ks++) {
            const uint32_t kb = ks * 32;
            uint32_t ah[2][4], al[2][4];
            #pragma unroll
            for (int mt = 0; mt < 2; mt++) {
                uint32_t ra = a_row_off + (uint32_t)(mt * 16 * ASTRIDE * 2) + kb;
                ldm4(ah[mt], sb + S_AH + ra);
                ldm4(al[mt], sb + S_AL + ra);
            }
            uint32_t bh[4][4], bl[4][4];
            #pragma unroll
            for (int i = 0; i < 4; i++) {
                uint32_t rbo = b_row_off + (uint32_t)(i * 16 * ASTRIDE * 2) + kb;
                ldm4(bh[i], sb + S_BH + rbo);
                ldm4(bl[i], sb + S_BL + rbo);
            }
            #pragma unroll
            for (int mt = 0; mt < 2; mt++) {
                #pragma unroll
                for (int i = 0; i < 4; i++) {
                    mma16816(acc[mt][2 * i],     ah[mt], bh[i][0], bh[i][1]);
                    mma16816(acc[mt][2 * i + 1], ah[mt], bh[i][2], bh[i][3]);
                    mma16816(acc[mt][2 * i],     ah[mt], bl[i][0], bl[i][1]);
                    mma16816(acc[mt][2 * i + 1], ah[mt], bl[i][2], bl[i][3]);
                    mma16816(acc[mt][2 * i],     al[mt], bh[i][0], bh[i][1]);
                    mma16816(acc[mt][2 * i + 1], al[mt], bh[i][2], bh[i][3]);
                }
            }
        }
    }

    // ---------------- stage D to smem (fp32, stride 132) ----------------------
    __syncthreads();
    float* Ds = (float*)smem;
    {
        const int r0 = wm * 32 + (lane >> 2);
        const int c0 = wn * 64 + (lane & 3) * 2;
        #pragma unroll
        for (int mt = 0; mt < 2; mt++) {
            #pragma unroll
            for (int g = 0; g < 8; g++) {
                int r = r0 + mt * 16;
                int cc = c0 + g * 8;
                *(float2*)&Ds[(r)     * DSTRIDE + cc] = make_float2(acc[mt][g][0], acc[mt][g][1]);
                *(float2*)&Ds[(r + 8) * DSTRIDE + cc] = make_float2(acc[mt][g][2], acc[mt][g][3]);
            }
        }
    }
    __syncthreads();

    // ---------------- epilogue: thread t -> (row t/2, half t&1) ---------------
    const int row  = tid >> 1;
    const int half = tid & 1;
    const int grow = rb + row;
    const bool ok  = grow < N_NODES;
    const float* drow = &Ds[row * DSTRIDE + half * 64];
    const size_t abase = (size_t)grow * 128 + half * 64;

    #pragma unroll
    for (int j4 = 0; j4 < 16; j4++) {
        float o[4];
        if (KT == 128) {
            #pragma unroll
            for (int q = 0; q < 4; q++)
                o[q] = drow[j4 * 4 + q] + __ldg(&bias[half * 64 + j4 * 4 + q]);
        } else {
            // LN stats computed once before the loop (hoisted below) — see note
            o[0] = 0.f;  // placeholder, overwritten below
        }
        if (KT == 128) {
            if (ok) {
                *(float4*)&h[abase + j4 * 4] = make_float4(o[0], o[1], o[2], o[3]);
                // aux: bf16 hi/lo + exp fp16
                __nv_bfloat16 b0 = __float2bfloat16(o[0]);
                __nv_bfloat16 b1 = __float2bfloat16(o[1]);
                __nv_bfloat16 b2 = __float2bfloat16(o[2]);
                __nv_bfloat16 b3 = __float2bfloat16(o[3]);
                ((uint2*)&g_Ahh[abase + j4 * 4])[0] =
                    make_uint2(pack_bf2(b0, b1), pack_bf2(b2, b3));
                ((uint2*)&g_Ahl[abase + j4 * 4])[0] = make_uint2(
                    pack_bf2(__float2bfloat16(o[0] - __bfloat162float(b0)),
                             __float2bfloat16(o[1] - __bfloat162float(b1))),
                    pack_bf2(__float2bfloat16(o[2] - __bfloat162float(b2)),
                             __float2bfloat16(o[3] - __bfloat162float(b3))));
                ((uint2*)&g_e[abase + j4 * 4])[0] = make_uint2(
                    pack_h2(__float2half(__expf(o[0])), __float2half(__expf(o[1]))),
                    pack_h2(__float2half(__expf(o[2])), __float2half(__expf(o[3]))));
            }
        }
    }

    if (KT == 256) {
        float s1 = 0.f, s2 = 0.f;
        #pragma unroll
        for (int j = 0; j < 64; j++) {
            float y = drow[j] + __ldg(&bias[half * 64 + j]);
            s1 += y;
            s2 += y * y;
        }
        s1 += __shfl_xor_sync(0xffffffffu, s1, 1);
        s2 += __shfl_xor_sync(0xffffffffu, s2, 1);
        float mu   = s1 * (1.0f / 128.0f);
        float var  = s2 * (1.0f / 128.0f) - mu * mu;
        float rstd = rsqrtf(var + LN_EPS);
        if (ok) {
            #pragma unroll
            for (int j4 = 0; j4 < 16; j4++) {
                float4 old = *(const float4*)&h[abase + j4 * 4];
                float o[4];
                #pragma unroll
                for (int q = 0; q < 4; q++) {
                    int col = half * 64 + j4 * 4 + q;
                    float y  = drow[j4 * 4 + q] + __ldg(&bias[col]);
                    float hn = (y - mu) * rstd * __ldg(&gamma[col]) + __ldg(&beta[col]);
                    hn = fmaxf(hn, 0.0f);
                    o[q] = 0.5f * ((&old.x)[q] + hn);
                }
                *(float4*)&h[abase + j4 * 4] = make_float4(o[0], o[1], o[2], o[3]);
                if (WAUX) {
                    __nv_bfloat16 b0 = __float2bfloat16(o[0]);
                    __nv_bfloat16 b1 = __float2bfloat16(o[1]);
                    __nv_bfloat16 b2 = __float2bfloat16(o[2]);
                    __nv_bfloat16 b3 = __float2bfloat16(o[3]);
                    ((uint2*)&g_Ahh[abase + j4 * 4])[0] =
                        make_uint2(pack_bf2(b0, b1), pack_bf2(b2, b3));
                    ((uint2*)&g_Ahl[abase + j4 * 4])[0] = make_uint2(
                        pack_bf2(__float2bfloat16(o[0] - __bfloat162float(b0)),
                                 __float2bfloat16(o[1] - __bfloat162float(b1))),
                        pack_bf2(__float2bfloat16(o[2] - __bfloat162float(b2)),
                                 __float2bfloat16(o[3] - __bfloat162float(b3))));
                    ((uint2*)&g_e[abase + j4 * 4])[0] = make_uint2(
                        pack_h2(__float2half(__expf(o[0])), __float2half(__expf(o[1]))),
                        pack_h2(__float2half(__expf(o[2])), __float2half(__expf(o[3]))));
                }
            }
        }
    }
}

// ---------------- launch ------------------------------------------------------
extern "C" void kernel_launch(void* const* d_in, const int* in_sizes, int n_in,
                              void* d_out, int out_size)
{
    const float* x        = (const float*)d_in[0];
    const int*   edge_src = (const int*)  d_in[1];
    const int*   edge_dst = (const int*)  d_in[2];
    const float* Wi       = (const float*)d_in[3];
    const float* bi       = (const float*)d_in[4];
    const float* Wl       = (const float*)d_in[5];
    const float* bl       = (const float*)d_in[6];
    const float* gamma    = (const float*)d_in[7];
    const float* beta     = (const float*)d_in[8];
    float* h = (float*)d_out;

    cudaFuncSetAttribute(k_mma_gemm<128, true>,  cudaFuncAttributeMaxDynamicSharedMemorySize, SMEM_BYTES);
    cudaFuncSetAttribute(k_mma_gemm<256, true>,  cudaFuncAttributeMaxDynamicSharedMemorySize, SMEM_BYTES);
    cudaFuncSetAttribute(k_mma_gemm<256, false>, cudaFuncAttributeMaxDynamicSharedMemorySize, SMEM_BYTES);

    const int nb = (N_NODES + 255) / 256;       // 196

    k_prep_b<<<(4 * 128 * 256) / 256, 256>>>(Wi, Wl);
    k_prep_ax<<<(N_NODES * 32 + 255) / 256, 256>>>(x);
    k_zero_counts<<<nb, 256>>>();
    k_hist<<<(N_EDGES + 255) / 256, 256>>>(edge_dst);
    k_scan1<<<nb, 256>>>();
    k_scan2<<<1, 256>>>();
    k_scan3<<<nb, 256>>>();
    k_scatter<<<(N_EDGES + 255) / 256, 256>>>(edge_src, edge_dst);

    const int gb = (N_NODES + 127) / 128;       // 391

    __nv_bfloat16* bh0;  __nv_bfloat16* bl0;
    cudaGetSymbolAddress((void**)&bh0, g_Bh);
    cudaGetSymbolAddress((void**)&bl0, g_Bl);

    k_mma_gemm<128, true><<<gb, 256, SMEM_BYTES>>>(h, bh0, bl0, bi, nullptr, nullptr);

    for (int l = 0; l < N_LAYERS; l++) {
        k_lse<<<(N_NODES + 1) / 2, 128>>>();
        if (l < N_LAYERS - 1) {
            k_mma_gemm<256, true><<<gb, 256, SMEM_BYTES>>>(
                h,
                bh0 + (size_t)(l + 1) * 128 * 256,
                bl0 + (size_t)(l + 1) * 128 * 256,
                bl + l * 128, gamma + l * 128, beta + l * 128);
        } else {
            k_mma_gemm<256, false><<<gb, 256, SMEM_BYTES>>>(
                h,
                bh0 + (size_t)(l + 1) * 128 * 256,
                bl0 + (size_t)(l + 1) * 128 * 256,
                bl + l * 128, gamma + l * 128, beta + l * 128);
        }
    }
}

// round 6
// speedup vs baseline: 1.6475x; 1.0571x over previous
#include <cuda_runtime.h>
#include <cuda_bf16.h>
#include <cuda_fp16.h>
#include <math.h>
#include <stdint.h>

#define N_NODES 50000
#define N_EDGES 800000
#define HID 128
#define N_LAYERS 3
#define LN_EPS 1e-5f

// ---------------- scratch (static device globals; no runtime alloc) ----------
__device__ int   g_counts[N_NODES];
__device__ int   g_rowptr[N_NODES + 1];
__device__ int   g_cursor[N_NODES];
__device__ int   g_bsum[256];
__device__ int   g_bsumx[256];
__device__ int   g_srcsorted[N_EDGES];
// h (A, first 128 k) as bf16 hi/lo ; agg (A, second 128 k) as bf16 hi/lo
__device__ __nv_bfloat16 g_Ahh[(size_t)N_NODES * HID];
__device__ __nv_bfloat16 g_Ahl[(size_t)N_NODES * HID];
__device__ __nv_bfloat16 g_Agh[(size_t)N_NODES * HID];
__device__ __nv_bfloat16 g_Agl[(size_t)N_NODES * HID];
// exp(h) table, fp16
__device__ __half g_e[(size_t)N_NODES * HID];
// preconverted weights, B-layout [slot][n=128][k=256] bf16 hi/lo (slot0=Wi, k<128)
__device__ __nv_bfloat16 g_Bh[4 * 128 * 256];
__device__ __nv_bfloat16 g_Bl[4 * 128 * 256];

// ================= helpers ====================================================
__device__ __forceinline__ uint32_t smem_u32(const void* p) {
    uint32_t a;
    asm("{ .reg .u64 t; cvta.to.shared.u64 t, %1; cvt.u32.u64 %0, t; }" : "=r"(a) : "l"(p));
    return a;
}
__device__ __forceinline__ void ldm4(uint32_t* r, uint32_t addr) {
    asm volatile("ldmatrix.sync.aligned.m8n8.x4.shared.b16 {%0,%1,%2,%3}, [%4];"
                 : "=r"(r[0]), "=r"(r[1]), "=r"(r[2]), "=r"(r[3]) : "r"(addr));
}
__device__ __forceinline__ void mma16816(float* d, const uint32_t* a, uint32_t b0, uint32_t b1) {
    asm volatile(
        "mma.sync.aligned.m16n8k16.row.col.f32.bf16.bf16.f32 "
        "{%0,%1,%2,%3}, {%4,%5,%6,%7}, {%8,%9}, {%0,%1,%2,%3};"
        : "+f"(d[0]), "+f"(d[1]), "+f"(d[2]), "+f"(d[3])
        : "r"(a[0]), "r"(a[1]), "r"(a[2]), "r"(a[3]), "r"(b0), "r"(b1));
}
__device__ __forceinline__ void cp16(uint32_t saddr, const void* gaddr) {
    asm volatile("cp.async.cg.shared.global [%0], [%1], 16;"
                 :: "r"(saddr), "l"(gaddr) : "memory");
}
__device__ __forceinline__ void cp_commit() {
    asm volatile("cp.async.commit_group;" ::: "memory");
}
template <int N>
__device__ __forceinline__ void cp_wait() {
    asm volatile("cp.async.wait_group %0;" :: "n"(N) : "memory");
}
__device__ __forceinline__ uint32_t pack_bf2(__nv_bfloat16 a, __nv_bfloat16 b) {
    return ((uint32_t)*(uint16_t*)&b << 16) | *(uint16_t*)&a;
}
__device__ __forceinline__ uint32_t pack_h2(__half a, __half b) {
    return ((uint32_t)*(uint16_t*)&b << 16) | *(uint16_t*)&a;
}

// ---------------- CSR build ---------------------------------------------------
__global__ void k_hist(const int* __restrict__ dst) {
    int e = blockIdx.x * blockDim.x + threadIdx.x;
    if (e < N_EDGES) atomicAdd(&g_counts[dst[e]], 1);
}
__global__ void k_scan1() {
    __shared__ int wsum[8];
    int b = blockIdx.x, t = threadIdx.x;
    int i = b * 256 + t;
    int v = (i < N_NODES) ? g_counts[i] : 0;
    int lane = t & 31, w = t >> 5;
    int x = v;
    #pragma unroll
    for (int off = 1; off < 32; off <<= 1) {
        int n = __shfl_up_sync(0xffffffffu, x, off);
        if (lane >= off) x += n;
    }
    if (lane == 31) wsum[w] = x;
    __syncthreads();
    if (t < 8) {
        int a = wsum[t];
        #pragma unroll
        for (int off = 1; off < 8; off <<= 1) {
            int n = __shfl_up_sync(0xffu, a, off);
            if (t >= off) a += n;
        }
        wsum[t] = a;
    }
    __syncthreads();
    int incl = x + (w > 0 ? wsum[w - 1] : 0);
    if (i < N_NODES) g_rowptr[i + 1] = incl;
    if (t == 255) g_bsum[b] = incl;
}
__global__ void k_scan2() {
    __shared__ int buf[256];
    int t = threadIdx.x;
    int nb = (N_NODES + 255) / 256;
    int v = (t < nb) ? g_bsum[t] : 0;
    buf[t] = v;
    __syncthreads();
    #pragma unroll
    for (int off = 1; off < 256; off <<= 1) {
        int x = (t >= off) ? buf[t - off] : 0;
        __syncthreads();
        buf[t] += x;
        __syncthreads();
    }
    g_bsumx[t] = buf[t] - v;   // exclusive
}
__global__ void k_scan3() {
    int b = blockIdx.x, t = threadIdx.x;
    int i = b * 256 + t;
    if (i < N_NODES) {
        int r = g_rowptr[i + 1] + g_bsumx[b];
        g_rowptr[i + 1] = r;
        g_cursor[i] = r - g_counts[i];
        g_counts[i] = 0;           // pre-zero for next graph replay
    }
    if (i == 0) g_rowptr[0] = 0;
}
__global__ void k_scatter(const int* __restrict__ src, const int* __restrict__ dst) {
    int e = blockIdx.x * blockDim.x + threadIdx.x;
    if (e < N_EDGES) {
        int p = atomicAdd(&g_cursor[dst[e]], 1);
        g_srcsorted[p] = src[e];
    }
}

// ---------------- weight preconversion: B[slot][n][k] = W[k][n] hi/lo ---------
__global__ void k_prep_b(const float* __restrict__ Wi, const float* __restrict__ Wl) {
    int idx = blockIdx.x * blockDim.x + threadIdx.x;   // 4*128*256
    int slot = idx >> 15;
    int rem  = idx & 32767;
    int n = rem >> 8;
    int k = rem & 255;
    float v;
    if (slot == 0) v = (k < 128) ? Wi[k * 128 + n] : 0.0f;
    else           v = Wl[(size_t)(slot - 1) * 256 * 128 + k * 128 + n];
    __nv_bfloat16 hi = __float2bfloat16(v);
    __nv_bfloat16 lo = __float2bfloat16(v - __bfloat162float(hi));
    g_Bh[idx] = hi;
    g_Bl[idx] = lo;
}

// ---------------- x -> bf16 hi/lo (input projection A operand) ----------------
__global__ void k_prep_ax(const float* __restrict__ x) {
    int idx = blockIdx.x * blockDim.x + threadIdx.x;   // N_NODES*32 float4 slots
    if (idx >= N_NODES * 32) return;
    float4 v = ((const float4*)x)[idx];
    __nv_bfloat16 h0 = __float2bfloat16(v.x);
    __nv_bfloat16 h1 = __float2bfloat16(v.y);
    __nv_bfloat16 h2 = __float2bfloat16(v.z);
    __nv_bfloat16 h3 = __float2bfloat16(v.w);
    ((uint2*)g_Ahh)[idx] = make_uint2(pack_bf2(h0, h1), pack_bf2(h2, h3));
    ((uint2*)g_Ahl)[idx] = make_uint2(
        pack_bf2(__float2bfloat16(v.x - __bfloat162float(h0)),
                 __float2bfloat16(v.y - __bfloat162float(h1))),
        pack_bf2(__float2bfloat16(v.z - __bfloat162float(h2)),
                 __float2bfloat16(v.w - __bfloat162float(h3))));
}

// ---------------- scatter-logsumexp: wide-gather of precomputed exp -----------
// 16 threads per node; thread owns 8 cols (one uint4 = 8 fp16 per edge).
__global__ void __launch_bounds__(256) k_lse() {
    const int t = threadIdx.x & 15;
    const int n = blockIdx.x * 16 + (threadIdx.x >> 4);
    if (n >= N_NODES) return;
    const int beg = g_rowptr[n];
    const int end = g_rowptr[n + 1];
    float a0[8], a1[8];
    #pragma unroll
    for (int j = 0; j < 8; j++) { a0[j] = 0.f; a1[j] = 0.f; }
    const uint4* E = (const uint4*)g_e;   // 16 uint4 per node row
    int e = beg;
    for (; e + 4 <= end; e += 4) {
        int s0 = __ldg(&g_srcsorted[e]);
        int s1 = __ldg(&g_srcsorted[e + 1]);
        int s2 = __ldg(&g_srcsorted[e + 2]);
        int s3 = __ldg(&g_srcsorted[e + 3]);
        uint4 v0 = __ldg(&E[s0 * 16 + t]);
        uint4 v1 = __ldg(&E[s1 * 16 + t]);
        uint4 v2 = __ldg(&E[s2 * 16 + t]);
        uint4 v3 = __ldg(&E[s3 * 16 + t]);
        #pragma unroll
        for (int w = 0; w < 4; w++) {
            float2 f0 = __half22float2(*(__half2*)((&v0.x) + w));
            float2 f1 = __half22float2(*(__half2*)((&v1.x) + w));
            float2 f2 = __half22float2(*(__half2*)((&v2.x) + w));
            float2 f3 = __half22float2(*(__half2*)((&v3.x) + w));
            a0[2 * w]     += f0.x + f1.x;
            a0[2 * w + 1] += f0.y + f1.y;
            a1[2 * w]     += f2.x + f3.x;
            a1[2 * w + 1] += f2.y + f3.y;
        }
    }
    for (; e < end; ++e) {
        int s = __ldg(&g_srcsorted[e]);
        uint4 v = __ldg(&E[s * 16 + t]);
        #pragma unroll
        for (int w = 0; w < 4; w++) {
            float2 f = __half22float2(*(__half2*)((&v.x) + w));
            a0[2 * w]     += f.x;
            a0[2 * w + 1] += f.y;
        }
    }
    uint4 oh, ol;
    uint32_t* ph = &oh.x;
    uint32_t* pl = &ol.x;
    if (beg == end) {
        oh = make_uint4(0, 0, 0, 0);
        ol = make_uint4(0, 0, 0, 0);
    } else {
        #pragma unroll
        for (int w = 0; w < 4; w++) {
            float vx = __logf(a0[2 * w] + a1[2 * w]);
            float vy = __logf(a0[2 * w + 1] + a1[2 * w + 1]);
            __nv_bfloat16 hx = __float2bfloat16(vx);
            __nv_bfloat16 hy = __float2bfloat16(vy);
            ph[w] = pack_bf2(hx, hy);
            pl[w] = pack_bf2(__float2bfloat16(vx - __bfloat162float(hx)),
                             __float2bfloat16(vy - __bfloat162float(hy)));
        }
    }
    size_t o = (size_t)n * 16 + t;   // uint4 index into [N,128] bf16
    ((uint4*)g_Agh)[o] = oh;
    ((uint4*)g_Agl)[o] = ol;
}

// ---------------- cp.async double-buffered MMA GEMM ---------------------------
// CTA: 256 threads (8 warps 4x2), 128x128 tile. K-chunk = 32, 2 smem stages.
// Stage: AH/AL/BH/BL, each 128 rows x 32 cols bf16, row stride 40 elems (80B).
#define RSTRIDE 40           // bf16 elems per smem row (80 B)
#define ARR_B   10240        // bytes per array (128*80)
#define STG_B   40960        // bytes per stage (4 arrays)
#define DSTRIDE 132          // fp32 elems per Ds row
#define SMEM_BYTES (2 * STG_B)   // 81920 >= 128*132*4 = 67584 (D aliases stages)

template <int KT, bool WAUX>
__global__ void __launch_bounds__(256, 2) k_mma_gemm(
    float* __restrict__ h,
    const __nv_bfloat16* __restrict__ Bh,
    const __nv_bfloat16* __restrict__ Bl,
    const float* __restrict__ bias,
    const float* __restrict__ gamma,
    const float* __restrict__ beta)
{
    extern __shared__ char smem[];
    const uint32_t sb = smem_u32(smem);
    const int tid  = threadIdx.x;
    const int lane = tid & 31;
    const int w    = tid >> 5;
    const int wm   = w >> 1;        // 0..3
    const int wn   = w & 1;         // 0..1
    const int rb   = blockIdx.x * 128;
    constexpr int NCH = KT / 32;

    // per-thread fill coords (2 x 16B per array per stage)
    const int f_row0 = tid >> 2,          f_q0 = tid & 3;
    const int f_row1 = (tid + 256) >> 2,  f_q1 = (tid + 256) & 3;
    int grow0 = rb + f_row0; if (grow0 >= N_NODES) grow0 = N_NODES - 1;
    int grow1 = rb + f_row1; if (grow1 >= N_NODES) grow1 = N_NODES - 1;

    auto prefetch = [&](int c, int stg) {
        const __nv_bfloat16* Ah = (KT == 256 && c >= 4) ? g_Agh : g_Ahh;
        const __nv_bfloat16* Al = (KT == 256 && c >= 4) ? g_Agl : g_Ahl;
        const int kb = (c * 32) & 127;            // within 128-col A source
        const uint32_t s0 = sb + stg * STG_B;
        // A hi/lo
        cp16(s0 +             f_row0 * 80 + f_q0 * 16, &Ah[(size_t)grow0 * 128 + kb + f_q0 * 8]);
        cp16(s0 +             f_row1 * 80 + f_q1 * 16, &Ah[(size_t)grow1 * 128 + kb + f_q1 * 8]);
        cp16(s0 + ARR_B +     f_row0 * 80 + f_q0 * 16, &Al[(size_t)grow0 * 128 + kb + f_q0 * 8]);
        cp16(s0 + ARR_B +     f_row1 * 80 + f_q1 * 16, &Al[(size_t)grow1 * 128 + kb + f_q1 * 8]);
        // B hi/lo (k index is c*32 within 256-k layout)
        cp16(s0 + 2 * ARR_B + f_row0 * 80 + f_q0 * 16, &Bh[(size_t)f_row0 * 256 + c * 32 + f_q0 * 8]);
        cp16(s0 + 2 * ARR_B + f_row1 * 80 + f_q1 * 16, &Bh[(size_t)f_row1 * 256 + c * 32 + f_q1 * 8]);
        cp16(s0 + 3 * ARR_B + f_row0 * 80 + f_q0 * 16, &Bl[(size_t)f_row0 * 256 + c * 32 + f_q0 * 8]);
        cp16(s0 + 3 * ARR_B + f_row1 * 80 + f_q1 * 16, &Bl[(size_t)f_row1 * 256 + c * 32 + f_q1 * 8]);
        cp_commit();
    };

    float acc[2][8][4];
    #pragma unroll
    for (int mt = 0; mt < 2; mt++)
        #pragma unroll
        for (int g = 0; g < 8; g++)
            #pragma unroll
            for (int q = 0; q < 4; q++) acc[mt][g][q] = 0.0f;

    const uint32_t a_row_off = (uint32_t)((wm * 32 + (lane & 15)) * 80 + (lane >> 4) * 16);
    const uint32_t b_row_off = (uint32_t)((wn * 64 + (lane & 7) + ((lane & 16) >> 1)) * 80
                                          + ((lane >> 3) & 1) * 16);

    prefetch(0, 0);
    for (int c = 0; c < NCH; c++) {
        if (c + 1 < NCH) { prefetch(c + 1, (c + 1) & 1); cp_wait<1>(); }
        else             { cp_wait<0>(); }
        __syncthreads();

        const uint32_t s0 = sb + (c & 1) * STG_B;
        #pragma unroll
        for (int ks = 0; ks < 2; ks++) {
            const uint32_t kb = ks * 32;
            uint32_t ah[2][4], al[2][4];
            #pragma unroll
            for (int mt = 0; mt < 2; mt++) {
                uint32_t ra = a_row_off + (uint32_t)(mt * 16 * 80) + kb;
                ldm4(ah[mt], s0 + ra);
                ldm4(al[mt], s0 + ARR_B + ra);
            }
            #pragma unroll
            for (int i = 0; i < 4; i++) {
                uint32_t rbo = b_row_off + (uint32_t)(i * 16 * 80) + kb;
                uint32_t bh[4], bl[4];
                ldm4(bh, s0 + 2 * ARR_B + rbo);
                ldm4(bl, s0 + 3 * ARR_B + rbo);
                #pragma unroll
                for (int mt = 0; mt < 2; mt++) {
                    mma16816(acc[mt][2 * i],     ah[mt], bh[0], bh[1]);
                    mma16816(acc[mt][2 * i + 1], ah[mt], bh[2], bh[3]);
                    mma16816(acc[mt][2 * i],     ah[mt], bl[0], bl[1]);
                    mma16816(acc[mt][2 * i + 1], ah[mt], bl[2], bl[3]);
                    mma16816(acc[mt][2 * i],     al[mt], bh[0], bh[1]);
                    mma16816(acc[mt][2 * i + 1], al[mt], bh[2], bh[3]);
                }
            }
        }
        __syncthreads();   // all warps done reading this stage before reuse
    }

    // ---------------- stage D to smem (fp32, stride 132) ----------------------
    float* Ds = (float*)smem;
    {
        const int r0 = wm * 32 + (lane >> 2);
        const int c0 = wn * 64 + (lane & 3) * 2;
        #pragma unroll
        for (int mt = 0; mt < 2; mt++) {
            #pragma unroll
            for (int g = 0; g < 8; g++) {
                int r = r0 + mt * 16;
                int cc = c0 + g * 8;
                *(float2*)&Ds[(r)     * DSTRIDE + cc] = make_float2(acc[mt][g][0], acc[mt][g][1]);
                *(float2*)&Ds[(r + 8) * DSTRIDE + cc] = make_float2(acc[mt][g][2], acc[mt][g][3]);
            }
        }
    }
    __syncthreads();

    // ---------------- epilogue: thread t -> (row t/2, half t&1) ---------------
    const int row  = tid >> 1;
    const int half = tid & 1;
    const int grow = rb + row;
    const bool ok  = grow < N_NODES;
    const float* drow = &Ds[row * DSTRIDE + half * 64];
    const size_t abase = (size_t)grow * 128 + half * 64;

    if (KT == 128) {
        if (ok) {
            #pragma unroll
            for (int j4 = 0; j4 < 16; j4++) {
                float o[4];
                #pragma unroll
                for (int q = 0; q < 4; q++)
                    o[q] = drow[j4 * 4 + q] + __ldg(&bias[half * 64 + j4 * 4 + q]);
                *(float4*)&h[abase + j4 * 4] = make_float4(o[0], o[1], o[2], o[3]);
                __nv_bfloat16 b0 = __float2bfloat16(o[0]);
                __nv_bfloat16 b1 = __float2bfloat16(o[1]);
                __nv_bfloat16 b2 = __float2bfloat16(o[2]);
                __nv_bfloat16 b3 = __float2bfloat16(o[3]);
                ((uint2*)&g_Ahh[abase + j4 * 4])[0] =
                    make_uint2(pack_bf2(b0, b1), pack_bf2(b2, b3));
                ((uint2*)&g_Ahl[abase + j4 * 4])[0] = make_uint2(
                    pack_bf2(__float2bfloat16(o[0] - __bfloat162float(b0)),
                             __float2bfloat16(o[1] - __bfloat162float(b1))),
                    pack_bf2(__float2bfloat16(o[2] - __bfloat162float(b2)),
                             __float2bfloat16(o[3] - __bfloat162float(b3))));
                ((uint2*)&g_e[abase + j4 * 4])[0] = make_uint2(
                    pack_h2(__float2half(__expf(o[0])), __float2half(__expf(o[1]))),
                    pack_h2(__float2half(__expf(o[2])), __float2half(__expf(o[3]))));
            }
        }
    } else {
        float s1 = 0.f, s2 = 0.f;
        #pragma unroll
        for (int j = 0; j < 64; j++) {
            float y = drow[j] + __ldg(&bias[half * 64 + j]);
            s1 += y;
            s2 += y * y;
        }
        s1 += __shfl_xor_sync(0xffffffffu, s1, 1);
        s2 += __shfl_xor_sync(0xffffffffu, s2, 1);
        float mu   = s1 * (1.0f / 128.0f);
        float var  = s2 * (1.0f / 128.0f) - mu * mu;
        float rstd = rsqrtf(var + LN_EPS);
        if (ok) {
            #pragma unroll
            for (int j4 = 0; j4 < 16; j4++) {
                float4 old = *(const float4*)&h[abase + j4 * 4];
                float o[4];
                #pragma unroll
                for (int q = 0; q < 4; q++) {
                    int col = half * 64 + j4 * 4 + q;
                    float y  = drow[j4 * 4 + q] + __ldg(&bias[col]);
                    float hn = (y - mu) * rstd * __ldg(&gamma[col]) + __ldg(&beta[col]);
                    hn = fmaxf(hn, 0.0f);
                    o[q] = 0.5f * ((&old.x)[q] + hn);
                }
                *(float4*)&h[abase + j4 * 4] = make_float4(o[0], o[1], o[2], o[3]);
                if (WAUX) {
                    __nv_bfloat16 b0 = __float2bfloat16(o[0]);
                    __nv_bfloat16 b1 = __float2bfloat16(o[1]);
                    __nv_bfloat16 b2 = __float2bfloat16(o[2]);
                    __nv_bfloat16 b3 = __float2bfloat16(o[3]);
                    ((uint2*)&g_Ahh[abase + j4 * 4])[0] =
                        make_uint2(pack_bf2(b0, b1), pack_bf2(b2, b3));
                    ((uint2*)&g_Ahl[abase + j4 * 4])[0] = make_uint2(
                        pack_bf2(__float2bfloat16(o[0] - __bfloat162float(b0)),
                                 __float2bfloat16(o[1] - __bfloat162float(b1))),
                        pack_bf2(__float2bfloat16(o[2] - __bfloat162float(b2)),
                                 __float2bfloat16(o[3] - __bfloat162float(b3))));
                    ((uint2*)&g_e[abase + j4 * 4])[0] = make_uint2(
                        pack_h2(__float2half(__expf(o[0])), __float2half(__expf(o[1]))),
                        pack_h2(__float2half(__expf(o[2])), __float2half(__expf(o[3]))));
                }
            }
        }
    }
}

// ---------------- launch ------------------------------------------------------
extern "C" void kernel_launch(void* const* d_in, const int* in_sizes, int n_in,
                              void* d_out, int out_size)
{
    const float* x        = (const float*)d_in[0];
    const int*   edge_src = (const int*)  d_in[1];
    const int*   edge_dst = (const int*)  d_in[2];
    const float* Wi       = (const float*)d_in[3];
    const float* bi       = (const float*)d_in[4];
    const float* Wl       = (const float*)d_in[5];
    const float* bl       = (const float*)d_in[6];
    const float* gamma    = (const float*)d_in[7];
    const float* beta     = (const float*)d_in[8];
    float* h = (float*)d_out;

    cudaFuncSetAttribute(k_mma_gemm<128, true>,  cudaFuncAttributeMaxDynamicSharedMemorySize, SMEM_BYTES);
    cudaFuncSetAttribute(k_mma_gemm<256, true>,  cudaFuncAttributeMaxDynamicSharedMemorySize, SMEM_BYTES);
    cudaFuncSetAttribute(k_mma_gemm<256, false>, cudaFuncAttributeMaxDynamicSharedMemorySize, SMEM_BYTES);

    const int nb = (N_NODES + 255) / 256;       // 196
    const int gb = (N_NODES + 127) / 128;       // 391

    __nv_bfloat16* bh0;  __nv_bfloat16* bl0;
    cudaGetSymbolAddress((void**)&bh0, g_Bh);
    cudaGetSymbolAddress((void**)&bl0, g_Bl);

    // launch order puts the input-proj GEMM at index 5 for ncu (-s 5)
    k_prep_b<<<(4 * 128 * 256) / 256, 256>>>(Wi, Wl);            // 0
    k_prep_ax<<<(N_NODES * 32 + 255) / 256, 256>>>(x);           // 1
    k_hist<<<(N_EDGES + 255) / 256, 256>>>(edge_dst);            // 2
    k_scan1<<<nb, 256>>>();                                      // 3
    k_scan2<<<1, 256>>>();                                       // 4
    k_mma_gemm<128, true><<<gb, 256, SMEM_BYTES>>>(h, bh0, bl0, bi, nullptr, nullptr);  // 5
    k_scan3<<<nb, 256>>>();                                      // 6
    k_scatter<<<(N_EDGES + 255) / 256, 256>>>(edge_src, edge_dst);  // 7

    for (int l = 0; l < N_LAYERS; l++) {
        k_lse<<<(N_NODES + 15) / 16, 256>>>();
        if (l < N_LAYERS - 1) {
            k_mma_gemm<256, true><<<gb, 256, SMEM_BYTES>>>(
                h,
                bh0 + (size_t)(l + 1) * 128 * 256,
                bl0 + (size_t)(l + 1) * 128 * 256,
                bl + l * 128, gamma + l * 128, beta + l * 128);
        } else {
            k_mma_gemm<256, false><<<gb, 256, SMEM_BYTES>>>(
                h,
                bh0 + (size_t)(l + 1) * 128 * 256,
                bl0 + (size_t)(l + 1) * 128 * 256,
                bl + l * 128, gamma + l * 128, beta + l * 128);
        }
    }
}

// round 7
// speedup vs baseline: 1.6794x; 1.0193x over previous
#include <cuda_runtime.h>
#include <cuda_bf16.h>
#include <cuda_fp16.h>
#include <math.h>
#include <stdint.h>

#define N_NODES 50000
#define N_EDGES 800000
#define HID 128
#define N_LAYERS 3
#define LN_EPS 1e-5f

// ---------------- scratch (static device globals; no runtime alloc) ----------
__device__ int   g_counts[N_NODES];
__device__ int   g_rowptr[N_NODES + 1];
__device__ int   g_cursor[N_NODES];
__device__ int   g_bsum[256];
__device__ int   g_bsumx[256];
__device__ int   g_srcsorted[N_EDGES];
// h (A, first 128 k) as bf16 hi/lo ; agg (A, second 128 k) as bf16 hi/lo
__device__ __nv_bfloat16 g_Ahh[(size_t)N_NODES * HID];
__device__ __nv_bfloat16 g_Ahl[(size_t)N_NODES * HID];
__device__ __nv_bfloat16 g_Agh[(size_t)N_NODES * HID];
__device__ __nv_bfloat16 g_Agl[(size_t)N_NODES * HID];
// exp(h) table, fp16
__device__ __half g_e[(size_t)N_NODES * HID];
// preconverted weights, B-layout [slot][n=128][k=256] bf16 hi/lo (slot0=Wi, k<128)
__device__ __nv_bfloat16 g_Bh[4 * 128 * 256];
__device__ __nv_bfloat16 g_Bl[4 * 128 * 256];

// ================= helpers ====================================================
__device__ __forceinline__ uint32_t smem_u32(const void* p) {
    uint32_t a;
    asm("{ .reg .u64 t; cvta.to.shared.u64 t, %1; cvt.u32.u64 %0, t; }" : "=r"(a) : "l"(p));
    return a;
}
__device__ __forceinline__ void ldm4(uint32_t* r, uint32_t addr) {
    asm volatile("ldmatrix.sync.aligned.m8n8.x4.shared.b16 {%0,%1,%2,%3}, [%4];"
                 : "=r"(r[0]), "=r"(r[1]), "=r"(r[2]), "=r"(r[3]) : "r"(addr));
}
__device__ __forceinline__ void mma16816(float* d, const uint32_t* a, uint32_t b0, uint32_t b1) {
    asm volatile(
        "mma.sync.aligned.m16n8k16.row.col.f32.bf16.bf16.f32 "
        "{%0,%1,%2,%3}, {%4,%5,%6,%7}, {%8,%9}, {%0,%1,%2,%3};"
        : "+f"(d[0]), "+f"(d[1]), "+f"(d[2]), "+f"(d[3])
        : "r"(a[0]), "r"(a[1]), "r"(a[2]), "r"(a[3]), "r"(b0), "r"(b1));
}
__device__ __forceinline__ void cp16(uint32_t saddr, const void* gaddr) {
    asm volatile("cp.async.cg.shared.global [%0], [%1], 16;"
                 :: "r"(saddr), "l"(gaddr) : "memory");
}
__device__ __forceinline__ void cp_commit() {
    asm volatile("cp.async.commit_group;" ::: "memory");
}
template <int N>
__device__ __forceinline__ void cp_wait() {
    asm volatile("cp.async.wait_group %0;" :: "n"(N) : "memory");
}
__device__ __forceinline__ uint32_t pack_bf2(__nv_bfloat16 a, __nv_bfloat16 b) {
    return ((uint32_t)*(uint16_t*)&b << 16) | *(uint16_t*)&a;
}
__device__ __forceinline__ uint32_t pack_h2(__half a, __half b) {
    return ((uint32_t)*(uint16_t*)&b << 16) | *(uint16_t*)&a;
}
__device__ __forceinline__ float bf2f(__nv_bfloat16 v) { return __bfloat162float(v); }

// ---------------- CSR build ---------------------------------------------------
__global__ void k_hist(const int* __restrict__ dst) {
    int e = blockIdx.x * blockDim.x + threadIdx.x;
    if (e < N_EDGES) atomicAdd(&g_counts[dst[e]], 1);
}
__global__ void k_scan1() {
    __shared__ int wsum[8];
    int b = blockIdx.x, t = threadIdx.x;
    int i = b * 256 + t;
    int v = (i < N_NODES) ? g_counts[i] : 0;
    int lane = t & 31, w = t >> 5;
    int x = v;
    #pragma unroll
    for (int off = 1; off < 32; off <<= 1) {
        int n = __shfl_up_sync(0xffffffffu, x, off);
        if (lane >= off) x += n;
    }
    if (lane == 31) wsum[w] = x;
    __syncthreads();
    if (t < 8) {
        int a = wsum[t];
        #pragma unroll
        for (int off = 1; off < 8; off <<= 1) {
            int n = __shfl_up_sync(0xffu, a, off);
            if (t >= off) a += n;
        }
        wsum[t] = a;
    }
    __syncthreads();
    int incl = x + (w > 0 ? wsum[w - 1] : 0);
    if (i < N_NODES) g_rowptr[i + 1] = incl;
    if (t == 255) g_bsum[b] = incl;
}
__global__ void k_scan2() {
    __shared__ int buf[256];
    int t = threadIdx.x;
    int nb = (N_NODES + 255) / 256;
    int v = (t < nb) ? g_bsum[t] : 0;
    buf[t] = v;
    __syncthreads();
    #pragma unroll
    for (int off = 1; off < 256; off <<= 1) {
        int x = (t >= off) ? buf[t - off] : 0;
        __syncthreads();
        buf[t] += x;
        __syncthreads();
    }
    g_bsumx[t] = buf[t] - v;   // exclusive
}
__global__ void k_scan3() {
    int b = blockIdx.x, t = threadIdx.x;
    int i = b * 256 + t;
    if (i < N_NODES) {
        int r = g_rowptr[i + 1] + g_bsumx[b];
        g_rowptr[i + 1] = r;
        g_cursor[i] = r - g_counts[i];
        g_counts[i] = 0;           // pre-zero for next graph replay
    }
    if (i == 0) g_rowptr[0] = 0;
}
__global__ void k_scatter(const int* __restrict__ src, const int* __restrict__ dst) {
    int e = blockIdx.x * blockDim.x + threadIdx.x;
    if (e < N_EDGES) {
        int p = atomicAdd(&g_cursor[dst[e]], 1);
        g_srcsorted[p] = src[e];
    }
}

// ---------------- weight preconversion: B[slot][n][k] = W[k][n] hi/lo ---------
__global__ void k_prep_b(const float* __restrict__ Wi, const float* __restrict__ Wl) {
    int idx = blockIdx.x * blockDim.x + threadIdx.x;   // 4*128*256
    int slot = idx >> 15;
    int rem  = idx & 32767;
    int n = rem >> 8;
    int k = rem & 255;
    float v;
    if (slot == 0) v = (k < 128) ? Wi[k * 128 + n] : 0.0f;
    else           v = Wl[(size_t)(slot - 1) * 256 * 128 + k * 128 + n];
    __nv_bfloat16 hi = __float2bfloat16(v);
    __nv_bfloat16 lo = __float2bfloat16(v - bf2f(hi));
    g_Bh[idx] = hi;
    g_Bl[idx] = lo;
}

// ---------------- x -> bf16 hi/lo (input projection A operand) ----------------
__global__ void k_prep_ax(const float* __restrict__ x) {
    int idx = blockIdx.x * blockDim.x + threadIdx.x;   // N_NODES*32 float4 slots
    if (idx >= N_NODES * 32) return;
    float4 v = ((const float4*)x)[idx];
    __nv_bfloat16 h0 = __float2bfloat16(v.x);
    __nv_bfloat16 h1 = __float2bfloat16(v.y);
    __nv_bfloat16 h2 = __float2bfloat16(v.z);
    __nv_bfloat16 h3 = __float2bfloat16(v.w);
    ((uint2*)g_Ahh)[idx] = make_uint2(pack_bf2(h0, h1), pack_bf2(h2, h3));
    ((uint2*)g_Ahl)[idx] = make_uint2(
        pack_bf2(__float2bfloat16(v.x - bf2f(h0)), __float2bfloat16(v.y - bf2f(h1))),
        pack_bf2(__float2bfloat16(v.z - bf2f(h2)), __float2bfloat16(v.w - bf2f(h3))));
}

// ---------------- scatter-logsumexp: wide-gather of precomputed exp -----------
// 16 threads per node; thread owns 8 cols (one uint4 = 8 fp16 per edge).
__global__ void __launch_bounds__(256) k_lse() {
    const int t = threadIdx.x & 15;
    const int n = blockIdx.x * 16 + (threadIdx.x >> 4);
    if (n >= N_NODES) return;
    const int beg = g_rowptr[n];
    const int end = g_rowptr[n + 1];
    float a0[8], a1[8];
    #pragma unroll
    for (int j = 0; j < 8; j++) { a0[j] = 0.f; a1[j] = 0.f; }
    const uint4* E = (const uint4*)g_e;   // 16 uint4 per node row
    int e = beg;
    for (; e + 8 <= end; e += 8) {
        uint4 v[8];
        #pragma unroll
        for (int u = 0; u < 8; u++) {
            int s = __ldg(&g_srcsorted[e + u]);
            v[u] = __ldg(&E[s * 16 + t]);
        }
        #pragma unroll
        for (int w = 0; w < 4; w++) {
            #pragma unroll
            for (int u = 0; u < 8; u++) {
                float2 f = __half22float2(*(__half2*)((&v[u].x) + w));
                if (u & 1) { a1[2 * w] += f.x; a1[2 * w + 1] += f.y; }
                else       { a0[2 * w] += f.x; a0[2 * w + 1] += f.y; }
            }
        }
    }
    for (; e < end; ++e) {
        int s = __ldg(&g_srcsorted[e]);
        uint4 v = __ldg(&E[s * 16 + t]);
        #pragma unroll
        for (int w = 0; w < 4; w++) {
            float2 f = __half22float2(*(__half2*)((&v.x) + w));
            a0[2 * w]     += f.x;
            a0[2 * w + 1] += f.y;
        }
    }
    uint4 oh, ol;
    uint32_t* ph = &oh.x;
    uint32_t* pl = &ol.x;
    if (beg == end) {
        oh = make_uint4(0, 0, 0, 0);
        ol = make_uint4(0, 0, 0, 0);
    } else {
        #pragma unroll
        for (int w = 0; w < 4; w++) {
            float vx = __logf(a0[2 * w] + a1[2 * w]);
            float vy = __logf(a0[2 * w + 1] + a1[2 * w + 1]);
            __nv_bfloat16 hx = __float2bfloat16(vx);
            __nv_bfloat16 hy = __float2bfloat16(vy);
            ph[w] = pack_bf2(hx, hy);
            pl[w] = pack_bf2(__float2bfloat16(vx - bf2f(hx)),
                             __float2bfloat16(vy - bf2f(hy)));
        }
    }
    size_t o = (size_t)n * 16 + t;   // uint4 index into [N,128] bf16
    ((uint4*)g_Agh)[o] = oh;
    ((uint4*)g_Agl)[o] = ol;
}

// ---------------- cp.async double-buffered MMA GEMM ---------------------------
// CTA: 256 threads (8 warps 4x2), 128x128 tile. K-chunk = 32, 2 smem stages.
// Stage: AH/AL/BH/BL, each 128 rows x 32 cols bf16, row stride 40 elems (80B).
// Pipeline: wait -> sync -> prefetch(c+1) -> compute(c)   (one barrier/chunk)
#define ARR_B   10240        // bytes per array (128*80)
#define STG_B   40960        // bytes per stage (4 arrays)
#define DSTRIDE 132          // fp32 elems per Ds row
#define SMEM_BYTES (2 * STG_B)   // 81920 >= 128*132*4 = 67584 (D aliases stages)

// MODE: 0 = input proj (KT=128, write aux only)
//       1 = layer with aux (KT=256, residual from Ahh/Ahl, write aux)
//       2 = final layer   (KT=256, residual from Ahh/Ahl, write fp32 h only)
template <int MODE>
__global__ void __launch_bounds__(256, 2) k_mma_gemm(
    float* __restrict__ h,
    const __nv_bfloat16* __restrict__ Bh,
    const __nv_bfloat16* __restrict__ Bl,
    const float* __restrict__ bias,
    const float* __restrict__ gamma,
    const float* __restrict__ beta)
{
    extern __shared__ char smem[];
    const uint32_t sb = smem_u32(smem);
    const int tid  = threadIdx.x;
    const int lane = tid & 31;
    const int w    = tid >> 5;
    const int wm   = w >> 1;        // 0..3
    const int wn   = w & 1;         // 0..1
    const int rb   = blockIdx.x * 128;
    constexpr int KT  = (MODE == 0) ? 128 : 256;
    constexpr int NCH = KT / 32;

    // per-thread fill coords (2 x 16B per array per stage)
    const int f_row0 = tid >> 2,          f_q0 = tid & 3;
    const int f_row1 = (tid + 256) >> 2,  f_q1 = (tid + 256) & 3;
    int grow0 = rb + f_row0; if (grow0 >= N_NODES) grow0 = N_NODES - 1;
    int grow1 = rb + f_row1; if (grow1 >= N_NODES) grow1 = N_NODES - 1;

    auto prefetch = [&](int c, int stg) {
        const __nv_bfloat16* Ah = (KT == 256 && c >= 4) ? g_Agh : g_Ahh;
        const __nv_bfloat16* Al = (KT == 256 && c >= 4) ? g_Agl : g_Ahl;
        const int kb = (c * 32) & 127;
        const uint32_t s0 = sb + stg * STG_B;
        cp16(s0 +             f_row0 * 80 + f_q0 * 16, &Ah[(size_t)grow0 * 128 + kb + f_q0 * 8]);
        cp16(s0 +             f_row1 * 80 + f_q1 * 16, &Ah[(size_t)grow1 * 128 + kb + f_q1 * 8]);
        cp16(s0 + ARR_B +     f_row0 * 80 + f_q0 * 16, &Al[(size_t)grow0 * 128 + kb + f_q0 * 8]);
        cp16(s0 + ARR_B +     f_row1 * 80 + f_q1 * 16, &Al[(size_t)grow1 * 128 + kb + f_q1 * 8]);
        cp16(s0 + 2 * ARR_B + f_row0 * 80 + f_q0 * 16, &Bh[(size_t)f_row0 * 256 + c * 32 + f_q0 * 8]);
        cp16(s0 + 2 * ARR_B + f_row1 * 80 + f_q1 * 16, &Bh[(size_t)f_row1 * 256 + c * 32 + f_q1 * 8]);
        cp16(s0 + 3 * ARR_B + f_row0 * 80 + f_q0 * 16, &Bl[(size_t)f_row0 * 256 + c * 32 + f_q0 * 8]);
        cp16(s0 + 3 * ARR_B + f_row1 * 80 + f_q1 * 16, &Bl[(size_t)f_row1 * 256 + c * 32 + f_q1 * 8]);
        cp_commit();
    };

    float acc[2][8][4];
    #pragma unroll
    for (int mt = 0; mt < 2; mt++)
        #pragma unroll
        for (int g = 0; g < 8; g++)
            #pragma unroll
            for (int q = 0; q < 4; q++) acc[mt][g][q] = 0.0f;

    const uint32_t a_row_off = (uint32_t)((wm * 32 + (lane & 15)) * 80 + (lane >> 4) * 16);
    const uint32_t b_row_off = (uint32_t)((wn * 64 + (lane & 7) + ((lane & 16) >> 1)) * 80
                                          + ((lane >> 3) & 1) * 16);

    prefetch(0, 0);
    for (int c = 0; c < NCH; c++) {
        cp_wait<0>();
        __syncthreads();
        if (c + 1 < NCH) prefetch(c + 1, (c + 1) & 1);

        const uint32_t s0 = sb + (c & 1) * STG_B;
        #pragma unroll
        for (int ks = 0; ks < 2; ks++) {
            const uint32_t kb = ks * 32;
            uint32_t ah[2][4], al[2][4];
            #pragma unroll
            for (int mt = 0; mt < 2; mt++) {
                uint32_t ra = a_row_off + (uint32_t)(mt * 16 * 80) + kb;
                ldm4(ah[mt], s0 + ra);
                ldm4(al[mt], s0 + ARR_B + ra);
            }
            #pragma unroll
            for (int i = 0; i < 4; i++) {
                uint32_t rbo = b_row_off + (uint32_t)(i * 16 * 80) + kb;
                uint32_t bh[4], bl[4];
                ldm4(bh, s0 + 2 * ARR_B + rbo);
                ldm4(bl, s0 + 3 * ARR_B + rbo);
                #pragma unroll
                for (int mt = 0; mt < 2; mt++) {
                    mma16816(acc[mt][2 * i],     ah[mt], bh[0], bh[1]);
                    mma16816(acc[mt][2 * i + 1], ah[mt], bh[2], bh[3]);
                    mma16816(acc[mt][2 * i],     ah[mt], bl[0], bl[1]);
                    mma16816(acc[mt][2 * i + 1], ah[mt], bl[2], bl[3]);
                    mma16816(acc[mt][2 * i],     al[mt], bh[0], bh[1]);
                    mma16816(acc[mt][2 * i + 1], al[mt], bh[2], bh[3]);
                }
            }
        }
    }

    // ---------------- stage D to smem (fp32, stride 132) ----------------------
    __syncthreads();   // compute done in all warps before aliasing stages with Ds
    float* Ds = (float*)smem;
    {
        const int r0 = wm * 32 + (lane >> 2);
        const int c0 = wn * 64 + (lane & 3) * 2;
        #pragma unroll
        for (int mt = 0; mt < 2; mt++) {
            #pragma unroll
            for (int g = 0; g < 8; g++) {
                int r = r0 + mt * 16;
                int cc = c0 + g * 8;
                *(float2*)&Ds[(r)     * DSTRIDE + cc] = make_float2(acc[mt][g][0], acc[mt][g][1]);
                *(float2*)&Ds[(r + 8) * DSTRIDE + cc] = make_float2(acc[mt][g][2], acc[mt][g][3]);
            }
        }
    }
    __syncthreads();

    // ---------------- epilogue: thread t -> (row t/2, half t&1) ---------------
    const int row  = tid >> 1;
    const int half = tid & 1;
    const int grow = rb + row;
    const bool ok  = grow < N_NODES;
    const float* drow = &Ds[row * DSTRIDE + half * 64];
    const size_t abase = (size_t)grow * 128 + half * 64;

    if (MODE == 0) {
        if (ok) {
            #pragma unroll
            for (int j4 = 0; j4 < 16; j4++) {
                float o[4];
                #pragma unroll
                for (int q = 0; q < 4; q++)
                    o[q] = drow[j4 * 4 + q] + __ldg(&bias[half * 64 + j4 * 4 + q]);
                __nv_bfloat16 b0 = __float2bfloat16(o[0]);
                __nv_bfloat16 b1 = __float2bfloat16(o[1]);
                __nv_bfloat16 b2 = __float2bfloat16(o[2]);
                __nv_bfloat16 b3 = __float2bfloat16(o[3]);
                ((uint2*)&g_Ahh[abase + j4 * 4])[0] =
                    make_uint2(pack_bf2(b0, b1), pack_bf2(b2, b3));
                ((uint2*)&g_Ahl[abase + j4 * 4])[0] = make_uint2(
                    pack_bf2(__float2bfloat16(o[0] - bf2f(b0)),
                             __float2bfloat16(o[1] - bf2f(b1))),
                    pack_bf2(__float2bfloat16(o[2] - bf2f(b2)),
                             __float2bfloat16(o[3] - bf2f(b3))));
                ((uint2*)&g_e[abase + j4 * 4])[0] = make_uint2(
                    pack_h2(__float2half(__expf(o[0])), __float2half(__expf(o[1]))),
                    pack_h2(__float2half(__expf(o[2])), __float2half(__expf(o[3]))));
            }
        }
    } else {
        float s1 = 0.f, s2 = 0.f;
        #pragma unroll
        for (int j = 0; j < 64; j++) {
            float y = drow[j] + __ldg(&bias[half * 64 + j]);
            s1 += y;
            s2 += y * y;
        }
        s1 += __shfl_xor_sync(0xffffffffu, s1, 1);
        s2 += __shfl_xor_sync(0xffffffffu, s2, 1);
        float mu   = s1 * (1.0f / 128.0f);
        float var  = s2 * (1.0f / 128.0f) - mu * mu;
        float rstd = rsqrtf(var + LN_EPS);
        if (ok) {
            #pragma unroll
            for (int j4 = 0; j4 < 16; j4++) {
                // old h reconstructed from bf16 hi/lo pair
                uint2 uh = ((const uint2*)&g_Ahh[abase + j4 * 4])[0];
                uint2 ul = ((const uint2*)&g_Ahl[abase + j4 * 4])[0];
                float o[4];
                #pragma unroll
                for (int q = 0; q < 4; q++) {
                    int col = half * 64 + j4 * 4 + q;
                    uint32_t wh = (&uh.x)[q >> 1];
                    uint32_t wl = (&ul.x)[q >> 1];
                    uint16_t sh = (q & 1) ? (uint16_t)(wh >> 16) : (uint16_t)wh;
                    uint16_t sl = (q & 1) ? (uint16_t)(wl >> 16) : (uint16_t)wl;
                    float old = bf2f(*(__nv_bfloat16*)&sh) + bf2f(*(__nv_bfloat16*)&sl);
                    float y  = drow[j4 * 4 + q] + __ldg(&bias[col]);
                    float hn = (y - mu) * rstd * __ldg(&gamma[col]) + __ldg(&beta[col]);
                    hn = fmaxf(hn, 0.0f);
                    o[q] = 0.5f * (old + hn);
                }
                if (MODE == 2) {
                    *(float4*)&h[abase + j4 * 4] = make_float4(o[0], o[1], o[2], o[3]);
                } else {
                    __nv_bfloat16 b0 = __float2bfloat16(o[0]);
                    __nv_bfloat16 b1 = __float2bfloat16(o[1]);
                    __nv_bfloat16 b2 = __float2bfloat16(o[2]);
                    __nv_bfloat16 b3 = __float2bfloat16(o[3]);
                    ((uint2*)&g_Ahh[abase + j4 * 4])[0] =
                        make_uint2(pack_bf2(b0, b1), pack_bf2(b2, b3));
                    ((uint2*)&g_Ahl[abase + j4 * 4])[0] = make_uint2(
                        pack_bf2(__float2bfloat16(o[0] - bf2f(b0)),
                                 __float2bfloat16(o[1] - bf2f(b1))),
                        pack_bf2(__float2bfloat16(o[2] - bf2f(b2)),
                                 __float2bfloat16(o[3] - bf2f(b3))));
                    ((uint2*)&g_e[abase + j4 * 4])[0] = make_uint2(
                        pack_h2(__float2half(__expf(o[0])), __float2half(__expf(o[1]))),
                        pack_h2(__float2half(__expf(o[2])), __float2half(__expf(o[3]))));
                }
            }
        }
    }
}

// ---------------- launch ------------------------------------------------------
extern "C" void kernel_launch(void* const* d_in, const int* in_sizes, int n_in,
                              void* d_out, int out_size)
{
    const float* x        = (const float*)d_in[0];
    const int*   edge_src = (const int*)  d_in[1];
    const int*   edge_dst = (const int*)  d_in[2];
    const float* Wi       = (const float*)d_in[3];
    const float* bi       = (const float*)d_in[4];
    const float* Wl       = (const float*)d_in[5];
    const float* bl       = (const float*)d_in[6];
    const float* gamma    = (const float*)d_in[7];
    const float* beta     = (const float*)d_in[8];
    float* h = (float*)d_out;

    cudaFuncSetAttribute(k_mma_gemm<0>, cudaFuncAttributeMaxDynamicSharedMemorySize, SMEM_BYTES);
    cudaFuncSetAttribute(k_mma_gemm<1>, cudaFuncAttributeMaxDynamicSharedMemorySize, SMEM_BYTES);
    cudaFuncSetAttribute(k_mma_gemm<2>, cudaFuncAttributeMaxDynamicSharedMemorySize, SMEM_BYTES);

    const int nb = (N_NODES + 255) / 256;       // 196
    const int gb = (N_NODES + 127) / 128;       // 391

    __nv_bfloat16* bh0;  __nv_bfloat16* bl0;
    cudaGetSymbolAddress((void**)&bh0, g_Bh);
    cudaGetSymbolAddress((void**)&bl0, g_Bl);

    // launch order puts the input-proj GEMM at index 3 (the slot ncu captures)
    k_prep_b<<<(4 * 128 * 256) / 256, 256>>>(Wi, Wl);            // 0
    k_prep_ax<<<(N_NODES * 32 + 255) / 256, 256>>>(x);           // 1
    k_hist<<<(N_EDGES + 255) / 256, 256>>>(edge_dst);            // 2
    k_mma_gemm<0><<<gb, 256, SMEM_BYTES>>>(h, bh0, bl0, bi, nullptr, nullptr);  // 3
    k_scan1<<<nb, 256>>>();                                      // 4
    k_scan2<<<1, 256>>>();                                       // 5
    k_scan3<<<nb, 256>>>();                                      // 6
    k_scatter<<<(N_EDGES + 255) / 256, 256>>>(edge_src, edge_dst);  // 7

    for (int l = 0; l < N_LAYERS; l++) {
        k_lse<<<(N_NODES + 15) / 16, 256>>>();
        if (l < N_LAYERS - 1) {
            k_mma_gemm<1><<<gb, 256, SMEM_BYTES>>>(
                h,
                bh0 + (size_t)(l + 1) * 128 * 256,
                bl0 + (size_t)(l + 1) * 128 * 256,
                bl + l * 128, gamma + l * 128, beta + l * 128);
        } else {
            k_mma_gemm<2><<<gb, 256, SMEM_BYTES>>>(
                h,
                bh0 + (size_t)(l + 1) * 128 * 256,
                bl0 + (size_t)(l + 1) * 128 * 256,
                bl + l * 128, gamma + l * 128, beta + l * 128);
        }
    }
}

// round 8
// speedup vs baseline: 1.8587x; 1.1068x over previous
#include <cuda_runtime.h>
#include <cuda_fp16.h>
#include <math.h>
#include <stdint.h>

#define N_NODES 50000
#define N_EDGES 800000
#define HID 128
#define N_LAYERS 3
#define LN_EPS 1e-5f

// ---------------- scratch (static device globals; no runtime alloc) ----------
__device__ int   g_counts[N_NODES];
__device__ int   g_rowptr[N_NODES + 1];
__device__ int   g_cursor[N_NODES];
__device__ int   g_bsum[256];
__device__ int   g_bsumx[256];
__device__ int   g_srcsorted[N_EDGES];
// h (A, first 128 k) as fp16 hi/lo ; agg (A, second 128 k) as fp16 hi/lo
__device__ __half g_Ahh[(size_t)N_NODES * HID];
__device__ __half g_Ahl[(size_t)N_NODES * HID];
__device__ __half g_Agh[(size_t)N_NODES * HID];
__device__ __half g_Agl[(size_t)N_NODES * HID];
// exp(h) table, fp16
__device__ __half g_e[(size_t)N_NODES * HID];
// preconverted weights fp16, B-layout [slot][n=128][k=256] (slot0=Wi, k<128)
__device__ __half g_B[4 * 128 * 256];

// ================= helpers ====================================================
__device__ __forceinline__ uint32_t smem_u32(const void* p) {
    uint32_t a;
    asm("{ .reg .u64 t; cvta.to.shared.u64 t, %1; cvt.u32.u64 %0, t; }" : "=r"(a) : "l"(p));
    return a;
}
__device__ __forceinline__ void ldm4(uint32_t* r, uint32_t addr) {
    asm volatile("ldmatrix.sync.aligned.m8n8.x4.shared.b16 {%0,%1,%2,%3}, [%4];"
                 : "=r"(r[0]), "=r"(r[1]), "=r"(r[2]), "=r"(r[3]) : "r"(addr));
}
__device__ __forceinline__ void mma16816(float* d, const uint32_t* a, uint32_t b0, uint32_t b1) {
    asm volatile(
        "mma.sync.aligned.m16n8k16.row.col.f32.f16.f16.f32 "
        "{%0,%1,%2,%3}, {%4,%5,%6,%7}, {%8,%9}, {%0,%1,%2,%3};"
        : "+f"(d[0]), "+f"(d[1]), "+f"(d[2]), "+f"(d[3])
        : "r"(a[0]), "r"(a[1]), "r"(a[2]), "r"(a[3]), "r"(b0), "r"(b1));
}
__device__ __forceinline__ void cp16(uint32_t saddr, const void* gaddr) {
    asm volatile("cp.async.cg.shared.global [%0], [%1], 16;"
                 :: "r"(saddr), "l"(gaddr) : "memory");
}
__device__ __forceinline__ void cp_commit() {
    asm volatile("cp.async.commit_group;" ::: "memory");
}
template <int N>
__device__ __forceinline__ void cp_wait() {
    asm volatile("cp.async.wait_group %0;" :: "n"(N) : "memory");
}
__device__ __forceinline__ uint32_t pack_h2(__half a, __half b) {
    return ((uint32_t)*(uint16_t*)&b << 16) | *(uint16_t*)&a;
}
__device__ __forceinline__ float h2f(__half v) { return __half2float(v); }

// ---------------- merged prep: weights->fp16, x->fp16 hi/lo, hist -------------
#define PB_BLK 512      // 4*128*256/256
#define PA_BLK 6250     // N_NODES*32/256
#define PH_BLK 3125     // N_EDGES/256
__global__ void k_prep(const float* __restrict__ x,
                       const float* __restrict__ Wi,
                       const float* __restrict__ Wl,
                       const int* __restrict__ dst) {
    int b = blockIdx.x, t = threadIdx.x;
    if (b < PB_BLK) {
        int idx = b * 256 + t;              // 4*128*256
        int slot = idx >> 15;
        int rem  = idx & 32767;
        int n = rem >> 8;
        int k = rem & 255;
        float v;
        if (slot == 0) v = (k < 128) ? Wi[k * 128 + n] : 0.0f;
        else           v = Wl[(size_t)(slot - 1) * 256 * 128 + k * 128 + n];
        g_B[idx] = __float2half(v);
    } else if (b < PB_BLK + PA_BLK) {
        int idx = (b - PB_BLK) * 256 + t;   // N_NODES*32 float4 slots
        float4 v = ((const float4*)x)[idx];
        __half h0 = __float2half(v.x);
        __half h1 = __float2half(v.y);
        __half h2 = __float2half(v.z);
        __half h3 = __float2half(v.w);
        ((uint2*)g_Ahh)[idx] = make_uint2(pack_h2(h0, h1), pack_h2(h2, h3));
        ((uint2*)g_Ahl)[idx] = make_uint2(
            pack_h2(__float2half(v.x - h2f(h0)), __float2half(v.y - h2f(h1))),
            pack_h2(__float2half(v.z - h2f(h2)), __float2half(v.w - h2f(h3))));
    } else {
        int e = (b - PB_BLK - PA_BLK) * 256 + t;
        if (e < N_EDGES) atomicAdd(&g_counts[dst[e]], 1);
    }
}

// ---------------- CSR scans ----------------------------------------------------
__global__ void k_scan1() {
    __shared__ int wsum[8];
    int b = blockIdx.x, t = threadIdx.x;
    int i = b * 256 + t;
    int v = (i < N_NODES) ? g_counts[i] : 0;
    int lane = t & 31, w = t >> 5;
    int x = v;
    #pragma unroll
    for (int off = 1; off < 32; off <<= 1) {
        int n = __shfl_up_sync(0xffffffffu, x, off);
        if (lane >= off) x += n;
    }
    if (lane == 31) wsum[w] = x;
    __syncthreads();
    if (t < 8) {
        int a = wsum[t];
        #pragma unroll
        for (int off = 1; off < 8; off <<= 1) {
            int n = __shfl_up_sync(0xffu, a, off);
            if (t >= off) a += n;
        }
        wsum[t] = a;
    }
    __syncthreads();
    int incl = x + (w > 0 ? wsum[w - 1] : 0);
    if (i < N_NODES) g_rowptr[i + 1] = incl;
    if (t == 255) g_bsum[b] = incl;
}
__global__ void k_scan2() {
    __shared__ int buf[256];
    int t = threadIdx.x;
    int nb = (N_NODES + 255) / 256;
    int v = (t < nb) ? g_bsum[t] : 0;
    buf[t] = v;
    __syncthreads();
    #pragma unroll
    for (int off = 1; off < 256; off <<= 1) {
        int x = (t >= off) ? buf[t - off] : 0;
        __syncthreads();
        buf[t] += x;
        __syncthreads();
    }
    g_bsumx[t] = buf[t] - v;   // exclusive
}
__global__ void k_scan3() {
    int b = blockIdx.x, t = threadIdx.x;
    int i = b * 256 + t;
    if (i < N_NODES) {
        int r = g_rowptr[i + 1] + g_bsumx[b];
        g_rowptr[i + 1] = r;
        g_cursor[i] = r - g_counts[i];
        g_counts[i] = 0;           // pre-zero for next graph replay
    }
    if (i == 0) g_rowptr[0] = 0;
}
__global__ void k_scatter(const int* __restrict__ src, const int* __restrict__ dst) {
    int e = blockIdx.x * blockDim.x + threadIdx.x;
    if (e < N_EDGES) {
        int p = atomicAdd(&g_cursor[dst[e]], 1);
        g_srcsorted[p] = src[e];
    }
}

// ---------------- scatter-logsumexp: wide-gather of precomputed exp -----------
// 16 threads per node; thread owns 8 cols (one uint4 = 8 fp16 per edge).
__global__ void __launch_bounds__(256) k_lse() {
    const int t = threadIdx.x & 15;
    const int n = blockIdx.x * 16 + (threadIdx.x >> 4);
    if (n >= N_NODES) return;
    const int beg = g_rowptr[n];
    const int end = g_rowptr[n + 1];
    float a0[8], a1[8];
    #pragma unroll
    for (int j = 0; j < 8; j++) { a0[j] = 0.f; a1[j] = 0.f; }
    const uint4* E = (const uint4*)g_e;   // 16 uint4 per node row
    int e = beg;
    for (; e + 8 <= end; e += 8) {
        uint4 v[8];
        #pragma unroll
        for (int u = 0; u < 8; u++) {
            int s = __ldg(&g_srcsorted[e + u]);
            v[u] = __ldg(&E[s * 16 + t]);
        }
        #pragma unroll
        for (int w = 0; w < 4; w++) {
            #pragma unroll
            for (int u = 0; u < 8; u++) {
                float2 f = __half22float2(*(__half2*)((&v[u].x) + w));
                if (u & 1) { a1[2 * w] += f.x; a1[2 * w + 1] += f.y; }
                else       { a0[2 * w] += f.x; a0[2 * w + 1] += f.y; }
            }
        }
    }
    for (; e < end; ++e) {
        int s = __ldg(&g_srcsorted[e]);
        uint4 v = __ldg(&E[s * 16 + t]);
        #pragma unroll
        for (int w = 0; w < 4; w++) {
            float2 f = __half22float2(*(__half2*)((&v.x) + w));
            a0[2 * w]     += f.x;
            a0[2 * w + 1] += f.y;
        }
    }
    uint4 oh, ol;
    uint32_t* ph = &oh.x;
    uint32_t* pl = &ol.x;
    if (beg == end) {
        oh = make_uint4(0, 0, 0, 0);
        ol = make_uint4(0, 0, 0, 0);
    } else {
        #pragma unroll
        for (int w = 0; w < 4; w++) {
            float vx = __logf(a0[2 * w] + a1[2 * w]);
            float vy = __logf(a0[2 * w + 1] + a1[2 * w + 1]);
            __half hx = __float2half(vx);
            __half hy = __float2half(vy);
            ph[w] = pack_h2(hx, hy);
            pl[w] = pack_h2(__float2half(vx - h2f(hx)),
                            __float2half(vy - h2f(hy)));
        }
    }
    size_t o = (size_t)n * 16 + t;   // uint4 index into [N,128] fp16
    ((uint4*)g_Agh)[o] = oh;
    ((uint4*)g_Agl)[o] = ol;
}

// ---------------- cp.async double-buffered MMA GEMM (fp16, 2 passes) ----------
// CTA: 256 threads (8 warps 4x2), 128x128 tile. K-chunk = 32, 2 smem stages.
// Stage: AH/AL/B, each 128 rows x 32 cols fp16, row stride 40 elems (80B).
// D = Ah*B + Al*B  (A fp16 hi/lo = ~fp32; B single fp16, err ~3e-4 rel)
#define ARR_B   10240        // bytes per array (128*80)
#define STG_B   30720        // bytes per stage (3 arrays)
#define DSTRIDE 132          // fp32 elems per Ds row
#define SMEM_BYTES 67584     // 128*132*4 (Ds) >= 2*STG_B = 61440

// MODE: 0 = input proj (KT=128, write aux only)
//       1 = layer with aux (KT=256, residual from Ahh/Ahl, write aux)
//       2 = final layer   (KT=256, residual from Ahh/Ahl, write fp32 h only)
template <int MODE>
__global__ void __launch_bounds__(256, 2) k_mma_gemm(
    float* __restrict__ h,
    const __half* __restrict__ B,
    const float* __restrict__ bias,
    const float* __restrict__ gamma,
    const float* __restrict__ beta)
{
    extern __shared__ char smem[];
    const uint32_t sb = smem_u32(smem);
    const int tid  = threadIdx.x;
    const int lane = tid & 31;
    const int w    = tid >> 5;
    const int wm   = w >> 1;        // 0..3
    const int wn   = w & 1;         // 0..1
    const int rb   = blockIdx.x * 128;
    constexpr int KT  = (MODE == 0) ? 128 : 256;
    constexpr int NCH = KT / 32;

    // per-thread fill coords (2 x 16B per array per stage)
    const int f_row0 = tid >> 2,          f_q0 = tid & 3;
    const int f_row1 = (tid + 256) >> 2,  f_q1 = (tid + 256) & 3;
    int grow0 = rb + f_row0; if (grow0 >= N_NODES) grow0 = N_NODES - 1;
    int grow1 = rb + f_row1; if (grow1 >= N_NODES) grow1 = N_NODES - 1;

    auto prefetch = [&](int c, int stg) {
        const __half* Ah = (KT == 256 && c >= 4) ? g_Agh : g_Ahh;
        const __half* Al = (KT == 256 && c >= 4) ? g_Agl : g_Ahl;
        const int kb = (c * 32) & 127;
        const uint32_t s0 = sb + stg * STG_B;
        cp16(s0 +             f_row0 * 80 + f_q0 * 16, &Ah[(size_t)grow0 * 128 + kb + f_q0 * 8]);
        cp16(s0 +             f_row1 * 80 + f_q1 * 16, &Ah[(size_t)grow1 * 128 + kb + f_q1 * 8]);
        cp16(s0 + ARR_B +     f_row0 * 80 + f_q0 * 16, &Al[(size_t)grow0 * 128 + kb + f_q0 * 8]);
        cp16(s0 + ARR_B +     f_row1 * 80 + f_q1 * 16, &Al[(size_t)grow1 * 128 + kb + f_q1 * 8]);
        cp16(s0 + 2 * ARR_B + f_row0 * 80 + f_q0 * 16, &B[(size_t)f_row0 * 256 + c * 32 + f_q0 * 8]);
        cp16(s0 + 2 * ARR_B + f_row1 * 80 + f_q1 * 16, &B[(size_t)f_row1 * 256 + c * 32 + f_q1 * 8]);
        cp_commit();
    };

    float acc[2][8][4];
    #pragma unroll
    for (int mt = 0; mt < 2; mt++)
        #pragma unroll
        for (int g = 0; g < 8; g++)
            #pragma unroll
            for (int q = 0; q < 4; q++) acc[mt][g][q] = 0.0f;

    const uint32_t a_row_off = (uint32_t)((wm * 32 + (lane & 15)) * 80 + (lane >> 4) * 16);
    const uint32_t b_row_off = (uint32_t)((wn * 64 + (lane & 7) + ((lane & 16) >> 1)) * 80
                                          + ((lane >> 3) & 1) * 16);

    prefetch(0, 0);
    for (int c = 0; c < NCH; c++) {
        cp_wait<0>();
        __syncthreads();
        if (c + 1 < NCH) prefetch(c + 1, (c + 1) & 1);

        const uint32_t s0 = sb + (c & 1) * STG_B;
        #pragma unroll
        for (int ks = 0; ks < 2; ks++) {
            const uint32_t kb = ks * 32;
            // batched ldmatrix: 8 independent LDSMs in flight
            uint32_t ah[2][4], al[2][4], bf[4][4];
            #pragma unroll
            for (int mt = 0; mt < 2; mt++)
                ldm4(ah[mt], s0 + a_row_off + (uint32_t)(mt * 16 * 80) + kb);
            #pragma unroll
            for (int mt = 0; mt < 2; mt++)
                ldm4(al[mt], s0 + ARR_B + a_row_off + (uint32_t)(mt * 16 * 80) + kb);
            #pragma unroll
            for (int i = 0; i < 4; i++)
                ldm4(bf[i], s0 + 2 * ARR_B + b_row_off + (uint32_t)(i * 16 * 80) + kb);
            #pragma unroll
            for (int mt = 0; mt < 2; mt++) {
                #pragma unroll
                for (int i = 0; i < 4; i++) {
                    mma16816(acc[mt][2 * i],     ah[mt], bf[i][0], bf[i][1]);
                    mma16816(acc[mt][2 * i + 1], ah[mt], bf[i][2], bf[i][3]);
                    mma16816(acc[mt][2 * i],     al[mt], bf[i][0], bf[i][1]);
                    mma16816(acc[mt][2 * i + 1], al[mt], bf[i][2], bf[i][3]);
                }
            }
        }
    }

    // ---------------- stage D to smem (fp32, stride 132) ----------------------
    __syncthreads();   // compute done in all warps before aliasing stages with Ds
    float* Ds = (float*)smem;
    {
        const int r0 = wm * 32 + (lane >> 2);
        const int c0 = wn * 64 + (lane & 3) * 2;
        #pragma unroll
        for (int mt = 0; mt < 2; mt++) {
            #pragma unroll
            for (int g = 0; g < 8; g++) {
                int r = r0 + mt * 16;
                int cc = c0 + g * 8;
                *(float2*)&Ds[(r)     * DSTRIDE + cc] = make_float2(acc[mt][g][0], acc[mt][g][1]);
                *(float2*)&Ds[(r + 8) * DSTRIDE + cc] = make_float2(acc[mt][g][2], acc[mt][g][3]);
            }
        }
    }
    __syncthreads();

    // ---------------- epilogue: thread t -> (row t/2, half t&1) ---------------
    const int row  = tid >> 1;
    const int half = tid & 1;
    const int grow = rb + row;
    const bool ok  = grow < N_NODES;
    const float* drow = &Ds[row * DSTRIDE + half * 64];
    const size_t abase = (size_t)grow * 128 + half * 64;

    if (MODE == 0) {
        if (ok) {
            #pragma unroll
            for (int j4 = 0; j4 < 16; j4++) {
                float4 bv = *(const float4*)&bias[half * 64 + j4 * 4];
                float o[4];
                #pragma unroll
                for (int q = 0; q < 4; q++)
                    o[q] = drow[j4 * 4 + q] + (&bv.x)[q];
                __half b0 = __float2half(o[0]);
                __half b1 = __float2half(o[1]);
                __half b2 = __float2half(o[2]);
                __half b3 = __float2half(o[3]);
                ((uint2*)&g_Ahh[abase + j4 * 4])[0] =
                    make_uint2(pack_h2(b0, b1), pack_h2(b2, b3));
                ((uint2*)&g_Ahl[abase + j4 * 4])[0] = make_uint2(
                    pack_h2(__float2half(o[0] - h2f(b0)), __float2half(o[1] - h2f(b1))),
                    pack_h2(__float2half(o[2] - h2f(b2)), __float2half(o[3] - h2f(b3))));
                ((uint2*)&g_e[abase + j4 * 4])[0] = make_uint2(
                    pack_h2(__float2half(__expf(o[0])), __float2half(__expf(o[1]))),
                    pack_h2(__float2half(__expf(o[2])), __float2half(__expf(o[3]))));
            }
        }
    } else {
        float s1 = 0.f, s2 = 0.f;
        #pragma unroll
        for (int j = 0; j < 64; j++) {
            float y = drow[j] + __ldg(&bias[half * 64 + j]);
            s1 += y;
            s2 += y * y;
        }
        s1 += __shfl_xor_sync(0xffffffffu, s1, 1);
        s2 += __shfl_xor_sync(0xffffffffu, s2, 1);
        float mu   = s1 * (1.0f / 128.0f);
        float var  = s2 * (1.0f / 128.0f) - mu * mu;
        float rstd = rsqrtf(var + LN_EPS);
        if (ok) {
            #pragma unroll
            for (int j4 = 0; j4 < 16; j4++) {
                float4 bv = *(const float4*)&bias[half * 64 + j4 * 4];
                float4 gv = *(const float4*)&gamma[half * 64 + j4 * 4];
                float4 ev = *(const float4*)&beta[half * 64 + j4 * 4];
                uint2 uh = ((const uint2*)&g_Ahh[abase + j4 * 4])[0];
                uint2 ul = ((const uint2*)&g_Ahl[abase + j4 * 4])[0];
                float o[4];
                #pragma unroll
                for (int q = 0; q < 4; q++) {
                    uint32_t wh = (&uh.x)[q >> 1];
                    uint32_t wl = (&ul.x)[q >> 1];
                    uint16_t sh = (q & 1) ? (uint16_t)(wh >> 16) : (uint16_t)wh;
                    uint16_t sl = (q & 1) ? (uint16_t)(wl >> 16) : (uint16_t)wl;
                    float old = h2f(*(__half*)&sh) + h2f(*(__half*)&sl);
                    float y  = drow[j4 * 4 + q] + (&bv.x)[q];
                    float hn = (y - mu) * rstd * (&gv.x)[q] + (&ev.x)[q];
                    hn = fmaxf(hn, 0.0f);
                    o[q] = 0.5f * (old + hn);
                }
                if (MODE == 2) {
                    *(float4*)&h[abase + j4 * 4] = make_float4(o[0], o[1], o[2], o[3]);
                } else {
                    __half b0 = __float2half(o[0]);
                    __half b1 = __float2half(o[1]);
                    __half b2 = __float2half(o[2]);
                    __half b3 = __float2half(o[3]);
                    ((uint2*)&g_Ahh[abase + j4 * 4])[0] =
                        make_uint2(pack_h2(b0, b1), pack_h2(b2, b3));
                    ((uint2*)&g_Ahl[abase + j4 * 4])[0] = make_uint2(
                        pack_h2(__float2half(o[0] - h2f(b0)), __float2half(o[1] - h2f(b1))),
                        pack_h2(__float2half(o[2] - h2f(b2)), __float2half(o[3] - h2f(b3))));
                    ((uint2*)&g_e[abase + j4 * 4])[0] = make_uint2(
                        pack_h2(__float2half(__expf(o[0])), __float2half(__expf(o[1]))),
                        pack_h2(__float2half(__expf(o[2])), __float2half(__expf(o[3]))));
                }
            }
        }
    }
}

// ---------------- launch ------------------------------------------------------
extern "C" void kernel_launch(void* const* d_in, const int* in_sizes, int n_in,
                              void* d_out, int out_size)
{
    const float* x        = (const float*)d_in[0];
    const int*   edge_src = (const int*)  d_in[1];
    const int*   edge_dst = (const int*)  d_in[2];
    const float* Wi       = (const float*)d_in[3];
    const float* bi       = (const float*)d_in[4];
    const float* Wl       = (const float*)d_in[5];
    const float* bl       = (const float*)d_in[6];
    const float* gamma    = (const float*)d_in[7];
    const float* beta     = (const float*)d_in[8];
    float* h = (float*)d_out;

    cudaFuncSetAttribute(k_mma_gemm<0>, cudaFuncAttributeMaxDynamicSharedMemorySize, SMEM_BYTES);
    cudaFuncSetAttribute(k_mma_gemm<1>, cudaFuncAttributeMaxDynamicSharedMemorySize, SMEM_BYTES);
    cudaFuncSetAttribute(k_mma_gemm<2>, cudaFuncAttributeMaxDynamicSharedMemorySize, SMEM_BYTES);

    const int nb = (N_NODES + 255) / 256;       // 196
    const int gb = (N_NODES + 127) / 128;       // 391

    __half* b0;
    cudaGetSymbolAddress((void**)&b0, g_B);

    // order keeps k_mma_gemm<0> at launch index 3 (the slot ncu captures)
    k_prep<<<PB_BLK + PA_BLK + PH_BLK, 256>>>(x, Wi, Wl, edge_dst);  // 0
    k_scan1<<<nb, 256>>>();                                          // 1
    k_scan2<<<1, 256>>>();                                           // 2
    k_mma_gemm<0><<<gb, 256, SMEM_BYTES>>>(h, b0, bi, nullptr, nullptr);  // 3
    k_scan3<<<nb, 256>>>();                                          // 4
    k_scatter<<<(N_EDGES + 255) / 256, 256>>>(edge_src, edge_dst);   // 5

    for (int l = 0; l < N_LAYERS; l++) {
        k_lse<<<(N_NODES + 15) / 16, 256>>>();
        if (l < N_LAYERS - 1) {
            k_mma_gemm<1><<<gb, 256, SMEM_BYTES>>>(
                h, b0 + (size_t)(l + 1) * 128 * 256,
                bl + l * 128, gamma + l * 128, beta + l * 128);
        } else {
            k_mma_gemm<2><<<gb, 256, SMEM_BYTES>>>(
                h, b0 + (size_t)(l + 1) * 128 * 256,
                bl + l * 128, gamma + l * 128, beta + l * 128);
        }
    }
}